// round 1
// baseline (speedup 1.0000x reference)
#include <cuda_runtime.h>

// Problem constants
#define NB   2
#define NL   1024
#define NC   512
#define NH   8
#define ND   64
#define NDE  80          // 64 scalar + 12 point dims, padded to 80 for float4
#define NCOL 1728        // 512*3 + 96*2 packed projection columns
#define NM   2048        // B*L tokens
#define NBH  16          // B*H

// ---------------- scratch (static device globals; no allocation) -------------
__device__ float g_x[NM * NC];          // layernormed features
__device__ float g_W[NC * NCOL];        // packed projection weights (scales folded)
__device__ float g_bias[NCOL];          // packed biases (scales folded)
__device__ float g_Q[NBH * NL * NDE];   // q_ext per (b,h): [l][80]
__device__ float g_K[NBH * NL * NDE];   // k_ext per (b,h): [l][80]
__device__ float g_V[NBH * NL * ND];    // v    per (b,h): [l][64]
__device__ float g_kb[NBH * NL];        // -pscale[h]*ksq key bias
__device__ float g_O[NM * NC];          // attention output in [b,l,h,d] layout

// ---------------- 1) pack weights + biases, folding scales ------------------
__global__ void pack_kernel(const float* __restrict__ wq, const float* __restrict__ wk,
                            const float* __restrict__ wv, const float* __restrict__ wqp,
                            const float* __restrict__ wkp,
                            const float* __restrict__ bq, const float* __restrict__ bk,
                            const float* __restrict__ bv, const float* __restrict__ bqp,
                            const float* __restrict__ bkp,
                            const float* __restrict__ pscale) {
    int idx = blockIdx.x * blockDim.x + threadIdx.x;
    if (idx < NCOL) {
        int n = idx; float v;
        if (n < 512)        v = bq[n] * 0.125f;                       // fold d^-1/2
        else if (n < 1024)  v = bk[n - 512];
        else if (n < 1536)  v = bv[n - 1024];
        else if (n < 1632) { int c = n - 1536; v = bqp[c] * 2.0f * pscale[c / 12]; }
        else               { int c = n - 1632; v = bkp[c]; }
        g_bias[n] = v;
    }
    if (idx < NC * NCOL) {
        int k = idx / NCOL, n = idx % NCOL;
        float v;
        if (n < 512)        v = wq[k * 512 + n] * 0.125f;
        else if (n < 1024)  v = wk[k * 512 + (n - 512)];
        else if (n < 1536)  v = wv[k * 512 + (n - 1024)];
        else if (n < 1632) { int c = n - 1536; v = wqp[k * 96 + c] * 2.0f * pscale[c / 12]; }
        else               { int c = n - 1632; v = wkp[k * 96 + c]; }
        g_W[k * NCOL + n] = v;
    }
}

// ---------------- 2) zero pad lanes 76..79 of Q/K ---------------------------
__global__ void zero_pads_kernel() {
    int idx = blockIdx.x * blockDim.x + threadIdx.x;
    float4 z = make_float4(0.f, 0.f, 0.f, 0.f);
    if (idx < NBH * NL)             *(float4*)&g_Q[(size_t)idx * NDE + 76] = z;
    else if (idx < 2 * NBH * NL)    *(float4*)&g_K[(size_t)(idx - NBH * NL) * NDE + 76] = z;
}

// ---------------- 3) LayerNorm ----------------------------------------------
__global__ void ln_kernel(const float* __restrict__ f, const float* __restrict__ g,
                          const float* __restrict__ bb) {
    int row = blockIdx.x, t = threadIdx.x;   // 256 threads, 2 elems each
    const float* xr = f + (size_t)row * NC;
    float v0 = xr[t], v1 = xr[t + 256];
    float s = v0 + v1, s2 = v0 * v0 + v1 * v1;
#pragma unroll
    for (int o = 16; o > 0; o >>= 1) {
        s  += __shfl_xor_sync(0xffffffffu, s, o);
        s2 += __shfl_xor_sync(0xffffffffu, s2, o);
    }
    __shared__ float sh[16];
    if ((t & 31) == 0) { sh[t >> 5] = s; sh[8 + (t >> 5)] = s2; }
    __syncthreads();
    float ts = 0.f, ts2 = 0.f;
#pragma unroll
    for (int i = 0; i < 8; i++) { ts += sh[i]; ts2 += sh[8 + i]; }
    float mu   = ts * (1.0f / NC);
    float var  = ts2 * (1.0f / NC) - mu * mu;
    float rstd = rsqrtf(var + 1e-5f);
    g_x[(size_t)row * NC + t]       = (v0 - mu) * rstd * g[t] + bb[t];
    g_x[(size_t)row * NC + t + 256] = (v1 - mu) * rstd * g[t + 256] + bb[t + 256];
}

// ---------------- shared GEMM mainloop (128x64 tile, BK=16, 256 thr) --------
__device__ __forceinline__ void gemm_mainloop(const float* __restrict__ A,
                                              const float* __restrict__ Bm,
                                              int N, int K, int m0, int n0,
                                              int tx, int ty,
                                              float acc[8][4],
                                              float* AsT /*[16][128]*/, float* Bs /*[16][64]*/) {
    int tid = ty * 16 + tx;
    for (int k0 = 0; k0 < K; k0 += 16) {
#pragma unroll
        for (int i = 0; i < 2; i++) {
            int idx = tid + i * 256;             // 512 float4 for A tile
            int row = idx >> 2, kg = (idx & 3) << 2;
            float4 fa = *(const float4*)(A + (size_t)(m0 + row) * K + k0 + kg);
            AsT[(kg + 0) * 128 + row] = fa.x;
            AsT[(kg + 1) * 128 + row] = fa.y;
            AsT[(kg + 2) * 128 + row] = fa.z;
            AsT[(kg + 3) * 128 + row] = fa.w;
        }
        {
            int row = tid >> 4, cg = (tid & 15) << 2;
            *(float4*)&Bs[row * 64 + cg] = *(const float4*)(Bm + (size_t)(k0 + row) * N + n0 + cg);
        }
        __syncthreads();
#pragma unroll
        for (int k = 0; k < 16; k++) {
            float4 a0 = *(float4*)&AsT[k * 128 + ty * 8];
            float4 a1 = *(float4*)&AsT[k * 128 + ty * 8 + 4];
            float4 b  = *(float4*)&Bs[k * 64 + tx * 4];
            float av[8] = {a0.x, a0.y, a0.z, a0.w, a1.x, a1.y, a1.z, a1.w};
            float bv[4] = {b.x, b.y, b.z, b.w};
#pragma unroll
            for (int i = 0; i < 8; i++)
#pragma unroll
                for (int j = 0; j < 4; j++) acc[i][j] += av[i] * bv[j];
        }
        __syncthreads();
    }
}

// ---------------- 4) projection GEMM, scatter epilogue ----------------------
__global__ void __launch_bounds__(256) gemm_proj_kernel() {
    __shared__ float AsT[16 * 128];
    __shared__ float Bs[16 * 64];
    int tid = threadIdx.x, tx = tid & 15, ty = tid >> 4;
    int m0 = blockIdx.y * 128, n0 = blockIdx.x * 64;
    float acc[8][4];
#pragma unroll
    for (int i = 0; i < 8; i++)
#pragma unroll
        for (int j = 0; j < 4; j++) acc[i][j] = 0.f;
    gemm_mainloop(g_x, g_W, NCOL, NC, m0, n0, tx, ty, acc, AsT, Bs);
#pragma unroll
    for (int i = 0; i < 8; i++) {
        int m = m0 + ty * 8 + i;
        int b = m >> 10, l = m & 1023;
#pragma unroll
        for (int j = 0; j < 4; j++) {
            int n = n0 + tx * 4 + j;
            float v = acc[i][j] + g_bias[n];
            if (n < 512) {                      // q scalar (pre-scaled by d^-1/2)
                int h = n >> 6, d = n & 63;
                g_Q[(size_t)((b * 8 + h) * NL + l) * NDE + d] = v;
            } else if (n < 1024) {              // k scalar
                int n2 = n - 512; int h = n2 >> 6, d = n2 & 63;
                g_K[(size_t)((b * 8 + h) * NL + l) * NDE + d] = v;
            } else if (n < 1536) {              // v
                int n2 = n - 1024; int h = n2 >> 6, d = n2 & 63;
                g_V[(size_t)((b * 8 + h) * NL + l) * ND + d] = v;
            } else if (n < 1632) {              // q point (pre-scaled by 2*pscale)
                int c = n - 1536; int h = c / 12, r = c - h * 12;
                g_Q[(size_t)((b * 8 + h) * NL + l) * NDE + 64 + r] = v;
            } else {                            // k point (raw, for ksq + dot)
                int c = n - 1632; int h = c / 12, r = c - h * 12;
                g_K[(size_t)((b * 8 + h) * NL + l) * NDE + 64 + r] = v;
            }
        }
    }
}

// ---------------- 5) key bias: -pscale[h] * |k_p|^2 -------------------------
__global__ void kbias_kernel(const float* __restrict__ pscale) {
    int row = blockIdx.x * blockDim.x + threadIdx.x;   // 0..16383
    if (row >= NBH * NL) return;
    int h = (row >> 10) & 7;
    const float* kp = &g_K[(size_t)row * NDE + 64];
    float s = 0.f;
#pragma unroll
    for (int r = 0; r < 12; r++) { float v = kp[r]; s += v * v; }
    g_kb[row] = -pscale[h] * s;
}

// ---------------- 6) flash attention (64q x 32k tiles, fp32) ----------------
__global__ void __launch_bounds__(256) flash_kernel() {
    __shared__ float QsT[80 * 64];   // [k][qrow], stride 64
    __shared__ float KsT[80 * 34];   // [k][krow], stride 34 (pad vs bank conflicts)
    __shared__ float Vs[32 * 64];    // [krow][dv]
    __shared__ float Ps[64 * 32];    // [qrow][krow]
    __shared__ float kbs[32];

    int tid = threadIdx.x, tx = tid & 15, ty = tid >> 4;
    int bh = blockIdx.y, i0 = blockIdx.x << 6;
    const float* Qg = g_Q + (size_t)(bh * NL + i0) * NDE;

    // load Q tile transposed (once)
    for (int idx = tid; idx < 64 * 20; idx += 256) {
        int row = idx / 20, kg = (idx % 20) << 2;
        float4 f = *(const float4*)(Qg + row * NDE + kg);
        QsT[(kg + 0) * 64 + row] = f.x;
        QsT[(kg + 1) * 64 + row] = f.y;
        QsT[(kg + 2) * 64 + row] = f.z;
        QsT[(kg + 3) * 64 + row] = f.w;
    }

    float m_i[4], l_i[4], o[4][4];
#pragma unroll
    for (int i = 0; i < 4; i++) {
        m_i[i] = -1e30f; l_i[i] = 0.f;
#pragma unroll
        for (int j = 0; j < 4; j++) o[i][j] = 0.f;
    }

    for (int jt = 0; jt < 32; jt++) {
        __syncthreads();   // previous Ps/Vs/KsT consumers done
        int j0 = jt << 5;
        const float* Kg = g_K + (size_t)(bh * NL + j0) * NDE;
        for (int idx = tid; idx < 32 * 20; idx += 256) {
            int row = idx / 20, kg = (idx % 20) << 2;
            float4 f = *(const float4*)(Kg + row * NDE + kg);
            KsT[(kg + 0) * 34 + row] = f.x;
            KsT[(kg + 1) * 34 + row] = f.y;
            KsT[(kg + 2) * 34 + row] = f.z;
            KsT[(kg + 3) * 34 + row] = f.w;
        }
        const float* Vg = g_V + (size_t)(bh * NL + j0) * ND;
        for (int idx = tid; idx < 512; idx += 256) {
            int row = idx >> 4, cg = (idx & 15) << 2;
            *(float4*)&Vs[row * 64 + cg] = *(const float4*)(Vg + row * ND + cg);
        }
        if (tid < 32) kbs[tid] = g_kb[bh * NL + j0 + tid];
        __syncthreads();

        // S = Q_ext @ K_ext^T  (76 live dims + 4 zero pads)
        float s[4][2];
        s[0][0]=s[0][1]=s[1][0]=s[1][1]=s[2][0]=s[2][1]=s[3][0]=s[3][1]=0.f;
#pragma unroll
        for (int k = 0; k < 80; k++) {
            float4 a = *(float4*)&QsT[k * 64 + ty * 4];
            float2 b = *(float2*)&KsT[k * 34 + tx * 2];
            s[0][0] += a.x * b.x; s[0][1] += a.x * b.y;
            s[1][0] += a.y * b.x; s[1][1] += a.y * b.y;
            s[2][0] += a.z * b.x; s[2][1] += a.z * b.y;
            s[3][0] += a.w * b.x; s[3][1] += a.w * b.y;
        }
        float kb0 = kbs[tx * 2], kb1 = kbs[tx * 2 + 1];
#pragma unroll
        for (int i = 0; i < 4; i++) {
            s[i][0] += kb0; s[i][1] += kb1;
            float mx = fmaxf(s[i][0], s[i][1]);
#pragma unroll
            for (int off = 8; off > 0; off >>= 1)
                mx = fmaxf(mx, __shfl_xor_sync(0xffffffffu, mx, off));
            float mnew = fmaxf(m_i[i], mx);
            float sc = __expf(m_i[i] - mnew);
            m_i[i] = mnew;
            s[i][0] = __expf(s[i][0] - mnew);
            s[i][1] = __expf(s[i][1] - mnew);
            float rs = s[i][0] + s[i][1];
#pragma unroll
            for (int off = 8; off > 0; off >>= 1)
                rs += __shfl_xor_sync(0xffffffffu, rs, off);
            l_i[i] = l_i[i] * sc + rs;
#pragma unroll
            for (int j = 0; j < 4; j++) o[i][j] *= sc;
            *(float2*)&Ps[(ty * 4 + i) * 32 + tx * 2] = make_float2(s[i][0], s[i][1]);
        }
        __syncthreads();

        // O += P @ V
#pragma unroll
        for (int k = 0; k < 32; k += 4) {
            float4 b0 = *(float4*)&Vs[(k + 0) * 64 + tx * 4];
            float4 b1 = *(float4*)&Vs[(k + 1) * 64 + tx * 4];
            float4 b2 = *(float4*)&Vs[(k + 2) * 64 + tx * 4];
            float4 b3 = *(float4*)&Vs[(k + 3) * 64 + tx * 4];
#pragma unroll
            for (int i = 0; i < 4; i++) {
                float4 a = *(float4*)&Ps[(ty * 4 + i) * 32 + k];
                o[i][0] += a.x * b0.x + a.y * b1.x + a.z * b2.x + a.w * b3.x;
                o[i][1] += a.x * b0.y + a.y * b1.y + a.z * b2.y + a.w * b3.y;
                o[i][2] += a.x * b0.z + a.y * b1.z + a.z * b2.z + a.w * b3.z;
                o[i][3] += a.x * b0.w + a.y * b1.w + a.z * b2.w + a.w * b3.w;
            }
        }
    }

    // epilogue: normalize, write to [b,l,h,d]
    int b = bh >> 3, h = bh & 7;
#pragma unroll
    for (int i = 0; i < 4; i++) {
        float inv = 1.0f / l_i[i];
        int l = i0 + ty * 4 + i;
        float4 w = make_float4(o[i][0] * inv, o[i][1] * inv, o[i][2] * inv, o[i][3] * inv);
        *(float4*)&g_O[(size_t)((b * NL + l) * NH + h) * ND + tx * 4] = w;
    }
}

// ---------------- 7) output projection --------------------------------------
__global__ void __launch_bounds__(256) gemm_out_kernel(const float* __restrict__ wo,
                                                       const float* __restrict__ bo,
                                                       float* __restrict__ out) {
    __shared__ float AsT[16 * 128];
    __shared__ float Bs[16 * 64];
    int tid = threadIdx.x, tx = tid & 15, ty = tid >> 4;
    int m0 = blockIdx.y * 128, n0 = blockIdx.x * 64;
    float acc[8][4];
#pragma unroll
    for (int i = 0; i < 8; i++)
#pragma unroll
        for (int j = 0; j < 4; j++) acc[i][j] = 0.f;
    gemm_mainloop(g_O, wo, NC, NC, m0, n0, tx, ty, acc, AsT, Bs);
#pragma unroll
    for (int i = 0; i < 8; i++) {
        int m = m0 + ty * 8 + i;
#pragma unroll
        for (int j = 0; j < 4; j++) {
            int n = n0 + tx * 4 + j;
            out[(size_t)m * NC + n] = acc[i][j] + bo[n];
        }
    }
}

// ---------------- launch -----------------------------------------------------
extern "C" void kernel_launch(void* const* d_in, const int* in_sizes, int n_in,
                              void* d_out, int out_size) {
    const float* features = (const float*)d_in[0];
    // d_in[1] coords: unused by reference
    const float* ln_g = (const float*)d_in[2];
    const float* ln_b = (const float*)d_in[3];
    const float* wq  = (const float*)d_in[4];  const float* bq  = (const float*)d_in[5];
    const float* wk  = (const float*)d_in[6];  const float* bk  = (const float*)d_in[7];
    const float* wv  = (const float*)d_in[8];  const float* bv  = (const float*)d_in[9];
    const float* wqp = (const float*)d_in[10]; const float* bqp = (const float*)d_in[11];
    const float* wkp = (const float*)d_in[12]; const float* bkp = (const float*)d_in[13];
    // d_in[14], d_in[15] (wvp, bvp): unused by reference
    const float* wo  = (const float*)d_in[16]; const float* bo  = (const float*)d_in[17];
    const float* pscale = (const float*)d_in[18];
    float* out = (float*)d_out;

    pack_kernel<<<(NC * NCOL + 255) / 256, 256>>>(wq, wk, wv, wqp, wkp,
                                                  bq, bk, bv, bqp, bkp, pscale);
    zero_pads_kernel<<<(2 * NBH * NL + 255) / 256, 256>>>();
    ln_kernel<<<NM, 256>>>(features, ln_g, ln_b);
    gemm_proj_kernel<<<dim3(NCOL / 64, NM / 128), 256>>>();
    kbias_kernel<<<(NBH * NL + 255) / 256, 256>>>(pscale);
    flash_kernel<<<dim3(NL / 64, NBH), 256>>>();
    gemm_out_kernel<<<dim3(NC / 64, NM / 128), 256>>>(wo, bo, out);
}

// round 4
// speedup vs baseline: 1.0625x; 1.0625x over previous
#include <cuda_runtime.h>
#include <cuda_bf16.h>
#include <cstdint>
#include <stdint.h>

// ---------------- problem constants -----------------------------------------
#define NB   2
#define NL   1024
#define NC   512
#define NH   8
#define ND   64
#define NDE  80          // 64 scalar + 12 point dims, padded to 80
#define NCOL 1728        // packed projection output columns
#define NCOLP 1792       // padded to 14*128 tiles
#define NM   2048        // B*L tokens
#define NBH  16          // B*H
#define GK   1536        // split-concat K' = 3*512

// ---------------- scratch ----------------------------------------------------
__device__ float g_Q[NBH * NL * NDE];        // q_ext fp32 [bh][l][80]
__device__ float g_K[NBH * NL * NDE];        // k_ext fp32
__device__ float g_V[NBH * NL * ND];         // v fp32
__device__ float g_kb[NBH * NL];             // -pscale*|kp|^2
__device__ float g_bias[NCOL];               // packed proj biases
__device__ __nv_bfloat16 g_xc[NM * GK];      // LN(x) split-concat [hi,lo,hi]
__device__ __nv_bfloat16 g_Wc[NCOLP * GK];   // packed W^T split-concat [hi,hi,lo]
__device__ __nv_bfloat16 g_Oc[NM * GK];      // attn out split-concat [hi,lo,hi]
__device__ __nv_bfloat16 g_WoC[NC * GK];     // wo^T split-concat [hi,hi,lo]

__device__ __forceinline__ void bf16split(float v, __nv_bfloat16& hi, __nv_bfloat16& lo) {
    hi = __float2bfloat16(v);
    lo = __float2bfloat16(v - __bfloat162float(hi));
}

// bf16 m16n8k16 HMMA (baseline PTX, no 'a'-target features)
__device__ __forceinline__ void mma16816(float* c, const uint32_t* a, const uint32_t* b) {
    asm volatile("mma.sync.aligned.m16n8k16.row.col.f32.bf16.bf16.f32 "
                 "{%0,%1,%2,%3}, {%4,%5,%6,%7}, {%8,%9}, {%0,%1,%2,%3};"
                 : "+f"(c[0]), "+f"(c[1]), "+f"(c[2]), "+f"(c[3])
                 : "r"(a[0]), "r"(a[1]), "r"(a[2]), "r"(a[3]), "r"(b[0]), "r"(b[1]));
}

// ---------------- 1) pack weights (split-concat bf16) + biases ---------------
__global__ void pack_kernel(const float* __restrict__ wq, const float* __restrict__ wk,
                            const float* __restrict__ wv, const float* __restrict__ wqp,
                            const float* __restrict__ wkp,
                            const float* __restrict__ bq, const float* __restrict__ bk,
                            const float* __restrict__ bv, const float* __restrict__ bqp,
                            const float* __restrict__ bkp,
                            const float* __restrict__ wo,
                            const float* __restrict__ pscale) {
    int idx = blockIdx.x * blockDim.x + threadIdx.x;
    const int T1 = NCOLP * NC;
    if (idx < T1) {
        int n = idx / NC, k = idx % NC;
        float v = 0.f;
        if (n < 512)        v = wq[k * 512 + n] * 0.125f;
        else if (n < 1024)  v = wk[k * 512 + (n - 512)];
        else if (n < 1536)  v = wv[k * 512 + (n - 1024)];
        else if (n < 1632) { int c = n - 1536; v = wqp[k * 96 + c] * 2.0f * pscale[c / 12]; }
        else if (n < 1728) { int c = n - 1632; v = wkp[k * 96 + c]; }
        __nv_bfloat16 hi, lo; bf16split(v, hi, lo);
        g_Wc[(size_t)n * GK + k]        = hi;
        g_Wc[(size_t)n * GK + 512 + k]  = hi;
        g_Wc[(size_t)n * GK + 1024 + k] = lo;
        if (k == 0 && n < NCOL) {
            float bb;
            if (n < 512)        bb = bq[n] * 0.125f;
            else if (n < 1024)  bb = bk[n - 512];
            else if (n < 1536)  bb = bv[n - 1024];
            else if (n < 1632) { int c = n - 1536; bb = bqp[c] * 2.0f * pscale[c / 12]; }
            else               { int c = n - 1632; bb = bkp[c]; }
            g_bias[n] = bb;
        }
    } else {
        int j = idx - T1;
        if (j < NC * NC) {
            int n = j / NC, k = j % NC;
            float v = wo[k * 512 + n];
            __nv_bfloat16 hi, lo; bf16split(v, hi, lo);
            g_WoC[(size_t)n * GK + k]        = hi;
            g_WoC[(size_t)n * GK + 512 + k]  = hi;
            g_WoC[(size_t)n * GK + 1024 + k] = lo;
        }
    }
}

// ---------------- 2) zero pad lanes 76..79 of Q/K ---------------------------
__global__ void zero_pads_kernel() {
    int idx = blockIdx.x * blockDim.x + threadIdx.x;
    float4 z = make_float4(0.f, 0.f, 0.f, 0.f);
    if (idx < NBH * NL)          *(float4*)&g_Q[(size_t)idx * NDE + 76] = z;
    else if (idx < 2 * NBH * NL) *(float4*)&g_K[(size_t)(idx - NBH * NL) * NDE + 76] = z;
}

// ---------------- 3) LayerNorm -> split-concat bf16 -------------------------
__global__ void ln_kernel(const float* __restrict__ f, const float* __restrict__ g,
                          const float* __restrict__ bb) {
    int row = blockIdx.x, t = threadIdx.x;
    const float* xr = f + (size_t)row * NC;
    float v0 = xr[t], v1 = xr[t + 256];
    float s = v0 + v1, s2 = v0 * v0 + v1 * v1;
#pragma unroll
    for (int o = 16; o > 0; o >>= 1) {
        s  += __shfl_xor_sync(0xffffffffu, s, o);
        s2 += __shfl_xor_sync(0xffffffffu, s2, o);
    }
    __shared__ float sh[16];
    if ((t & 31) == 0) { sh[t >> 5] = s; sh[8 + (t >> 5)] = s2; }
    __syncthreads();
    float ts = 0.f, ts2 = 0.f;
#pragma unroll
    for (int i = 0; i < 8; i++) { ts += sh[i]; ts2 += sh[8 + i]; }
    float mu   = ts * (1.0f / NC);
    float var  = ts2 * (1.0f / NC) - mu * mu;
    float rstd = rsqrtf(var + 1e-5f);
    float x0 = (v0 - mu) * rstd * g[t] + bb[t];
    float x1 = (v1 - mu) * rstd * g[t + 256] + bb[t + 256];
    size_t base = (size_t)row * GK;
    __nv_bfloat16 h0, l0, h1, l1;
    bf16split(x0, h0, l0); bf16split(x1, h1, l1);
    g_xc[base + t]          = h0;  g_xc[base + t + 256]          = h1;
    g_xc[base + 512 + t]    = l0;  g_xc[base + 512 + t + 256]    = l1;
    g_xc[base + 1024 + t]   = h0;  g_xc[base + 1024 + t + 256]   = h1;
}

// ---------------- mma.sync bf16-split GEMM (128x128 tile, K'=1536) ----------
// 256 threads = 8 warps in 2(M) x 4(N); warp tile 64x32; BK=32, double buffer.
// Smem rows padded to 40 bf16 -> conflict-free fragment LDS.
// MODE 0: A=g_xc, B=g_Wc -> scatter into g_Q/g_K/g_V (+g_bias)
// MODE 1: A=g_Oc, B=g_WoC -> out = D + bias2
#define SROW 40
template <int MODE>
__global__ void __launch_bounds__(256) gemm_mma(const float* __restrict__ bias2,
                                                float* __restrict__ outp) {
    __shared__ __nv_bfloat16 As[2][128 * SROW];
    __shared__ __nv_bfloat16 Bs[2][128 * SROW];
    int tid = threadIdx.x, lane = tid & 31, wid = tid >> 5;
    int wm = wid & 1, wn = wid >> 1;
    int m0 = blockIdx.y * 128, n0 = blockIdx.x * 128;
    const __nv_bfloat16* Ap = (MODE == 0 ? g_xc : g_Oc) + (size_t)m0 * GK;
    const __nv_bfloat16* Bp = (MODE == 0 ? g_Wc : g_WoC) + (size_t)n0 * GK;

    float c[4][4][4];
#pragma unroll
    for (int i = 0; i < 4; i++)
#pragma unroll
        for (int j = 0; j < 4; j++)
#pragma unroll
            for (int e = 0; e < 4; e++) c[i][j][e] = 0.f;

    // loader indices: idx = tid + i*256 (i=0,1); row = idx>>2, q = idx&3 (8 bf16 chunks)
    int lr0 = tid >> 2, lq0 = tid & 3;
    int lr1 = (tid + 256) >> 2, lq1 = lq0;   // (tid+256)&3 == tid&3

    // prologue: stage 0 straight to smem
    {
        *(uint4*)&As[0][lr0 * SROW + lq0 * 8] = *(const uint4*)(Ap + (size_t)lr0 * GK + lq0 * 8);
        *(uint4*)&As[0][lr1 * SROW + lq1 * 8] = *(const uint4*)(Ap + (size_t)lr1 * GK + lq1 * 8);
        *(uint4*)&Bs[0][lr0 * SROW + lq0 * 8] = *(const uint4*)(Bp + (size_t)lr0 * GK + lq0 * 8);
        *(uint4*)&Bs[0][lr1 * SROW + lq1 * 8] = *(const uint4*)(Bp + (size_t)lr1 * GK + lq1 * 8);
    }
    __syncthreads();

    const int NSTAGE = GK / 32;   // 48
    for (int s = 0; s < NSTAGE; s++) {
        int buf = s & 1;
        uint4 ra0, ra1, rb0, rb1;
        if (s + 1 < NSTAGE) {
            int k0 = (s + 1) * 32;
            ra0 = *(const uint4*)(Ap + (size_t)lr0 * GK + k0 + lq0 * 8);
            ra1 = *(const uint4*)(Ap + (size_t)lr1 * GK + k0 + lq1 * 8);
            rb0 = *(const uint4*)(Bp + (size_t)lr0 * GK + k0 + lq0 * 8);
            rb1 = *(const uint4*)(Bp + (size_t)lr1 * GK + k0 + lq1 * 8);
        }
#pragma unroll
        for (int ks = 0; ks < 2; ks++) {
            int kk = ks * 16 + (lane & 3) * 2;
            uint32_t a[4][4], b[4][2];
#pragma unroll
            for (int mf = 0; mf < 4; mf++) {
                int r = wm * 64 + mf * 16 + (lane >> 2);
                a[mf][0] = *(const uint32_t*)&As[buf][r * SROW + kk];
                a[mf][1] = *(const uint32_t*)&As[buf][(r + 8) * SROW + kk];
                a[mf][2] = *(const uint32_t*)&As[buf][r * SROW + kk + 8];
                a[mf][3] = *(const uint32_t*)&As[buf][(r + 8) * SROW + kk + 8];
            }
#pragma unroll
            for (int nf = 0; nf < 4; nf++) {
                int nr = wn * 32 + nf * 8 + (lane >> 2);
                b[nf][0] = *(const uint32_t*)&Bs[buf][nr * SROW + kk];
                b[nf][1] = *(const uint32_t*)&Bs[buf][nr * SROW + kk + 8];
            }
#pragma unroll
            for (int mf = 0; mf < 4; mf++)
#pragma unroll
                for (int nf = 0; nf < 4; nf++)
                    mma16816(c[mf][nf], a[mf], b[nf]);
        }
        if (s + 1 < NSTAGE) {
            int nb = buf ^ 1;
            *(uint4*)&As[nb][lr0 * SROW + lq0 * 8] = ra0;
            *(uint4*)&As[nb][lr1 * SROW + lq1 * 8] = ra1;
            *(uint4*)&Bs[nb][lr0 * SROW + lq0 * 8] = rb0;
            *(uint4*)&Bs[nb][lr1 * SROW + lq1 * 8] = rb1;
        }
        __syncthreads();
    }

    // epilogue
#pragma unroll
    for (int mf = 0; mf < 4; mf++) {
#pragma unroll
        for (int nf = 0; nf < 4; nf++) {
#pragma unroll
            for (int e = 0; e < 4; e++) {
                int m = m0 + wm * 64 + mf * 16 + (lane >> 2) + ((e >> 1) << 3);
                int n = n0 + wn * 32 + nf * 8 + ((lane & 3) << 1) + (e & 1);
                float v = c[mf][nf][e];
                if (MODE == 0) {
                    if (n < NCOL) {
                        v += g_bias[n];
                        int b = m >> 10, l = m & 1023;
                        if (n < 512) {
                            int h = n >> 6, d = n & 63;
                            g_Q[(size_t)((b * 8 + h) * NL + l) * NDE + d] = v;
                        } else if (n < 1024) {
                            int n2 = n - 512; int h = n2 >> 6, d = n2 & 63;
                            g_K[(size_t)((b * 8 + h) * NL + l) * NDE + d] = v;
                        } else if (n < 1536) {
                            int n2 = n - 1024; int h = n2 >> 6, d = n2 & 63;
                            g_V[(size_t)((b * 8 + h) * NL + l) * ND + d] = v;
                        } else if (n < 1632) {
                            int cc = n - 1536; int h = cc / 12, r = cc - h * 12;
                            g_Q[(size_t)((b * 8 + h) * NL + l) * NDE + 64 + r] = v;
                        } else {
                            int cc = n - 1632; int h = cc / 12, r = cc - h * 12;
                            g_K[(size_t)((b * 8 + h) * NL + l) * NDE + 64 + r] = v;
                        }
                    }
                } else {
                    outp[(size_t)m * NC + n] = v + bias2[n];
                }
            }
        }
    }
}

// ---------------- 5) key bias -----------------------------------------------
__global__ void kbias_kernel(const float* __restrict__ pscale) {
    int row = blockIdx.x * blockDim.x + threadIdx.x;
    if (row >= NBH * NL) return;
    int h = (row >> 10) & 7;
    const float* kp = &g_K[(size_t)row * NDE + 64];
    float s = 0.f;
#pragma unroll
    for (int r = 0; r < 12; r++) { float v = kp[r]; s += v * v; }
    g_kb[row] = -pscale[h] * s;
}

// ---------------- 6) flash attention (64q x 64k, fp32, no online max) -------
// dyn smem floats: QsT[80*64] | KsT[80*64] | Vs[64*64] | Ps[64*68] | kbs[64]
#define FQ_OFF 0
#define FK_OFF 5120
#define FV_OFF 10240
#define FP_OFF 14336
#define FB_OFF 18688
#define FLASH_SMEM ((18688 + 64) * 4)

__global__ void __launch_bounds__(256, 2) flash_kernel() {
    extern __shared__ float fsm[];
    float* QsT = fsm + FQ_OFF;
    float* KsT = fsm + FK_OFF;
    float* Vs  = fsm + FV_OFF;
    float* Ps  = fsm + FP_OFF;
    float* kbs = fsm + FB_OFF;

    int tid = threadIdx.x, tx = tid & 15, ty = tid >> 4;
    int bh = blockIdx.y, i0 = blockIdx.x << 6;
    const float* Qg = g_Q + (size_t)(bh * NL + i0) * NDE;

    for (int idx = tid; idx < 64 * 20; idx += 256) {
        int row = idx / 20, kg = (idx % 20) << 2;
        float4 f = *(const float4*)(Qg + row * NDE + kg);
        QsT[(kg + 0) * 64 + row] = f.x;
        QsT[(kg + 1) * 64 + row] = f.y;
        QsT[(kg + 2) * 64 + row] = f.z;
        QsT[(kg + 3) * 64 + row] = f.w;
    }

    float l_i[4] = {0.f, 0.f, 0.f, 0.f};
    float o[4][4];
#pragma unroll
    for (int i = 0; i < 4; i++)
#pragma unroll
        for (int j = 0; j < 4; j++) o[i][j] = 0.f;

    for (int jt = 0; jt < 16; jt++) {
        __syncthreads();
        int j0 = jt << 6;
        const float* Kg = g_K + (size_t)(bh * NL + j0) * NDE;
        for (int idx = tid; idx < 64 * 20; idx += 256) {
            int row = idx / 20, kg = (idx % 20) << 2;
            float4 f = *(const float4*)(Kg + row * NDE + kg);
            KsT[(kg + 0) * 64 + row] = f.x;
            KsT[(kg + 1) * 64 + row] = f.y;
            KsT[(kg + 2) * 64 + row] = f.z;
            KsT[(kg + 3) * 64 + row] = f.w;
        }
        const float* Vg = g_V + (size_t)(bh * NL + j0) * ND;
        for (int idx = tid; idx < 64 * 16; idx += 256) {
            int row = idx >> 4, cg = (idx & 15) << 2;
            *(float4*)&Vs[row * 64 + cg] = *(const float4*)(Vg + row * ND + cg);
        }
        if (tid < 64) kbs[tid] = g_kb[bh * NL + j0 + tid];
        __syncthreads();

        float s[4][4];
#pragma unroll
        for (int i = 0; i < 4; i++)
#pragma unroll
            for (int j = 0; j < 4; j++) s[i][j] = 0.f;
#pragma unroll 10
        for (int d = 0; d < 80; d++) {
            float4 a = *(float4*)&QsT[d * 64 + ty * 4];
            float4 b = *(float4*)&KsT[d * 64 + tx * 4];
            s[0][0] += a.x * b.x; s[0][1] += a.x * b.y; s[0][2] += a.x * b.z; s[0][3] += a.x * b.w;
            s[1][0] += a.y * b.x; s[1][1] += a.y * b.y; s[1][2] += a.y * b.z; s[1][3] += a.y * b.w;
            s[2][0] += a.z * b.x; s[2][1] += a.z * b.y; s[2][2] += a.z * b.z; s[2][3] += a.z * b.w;
            s[3][0] += a.w * b.x; s[3][1] += a.w * b.y; s[3][2] += a.w * b.z; s[3][3] += a.w * b.w;
        }
        float kb0 = kbs[tx * 4], kb1 = kbs[tx * 4 + 1], kb2 = kbs[tx * 4 + 2], kb3 = kbs[tx * 4 + 3];
#pragma unroll
        for (int i = 0; i < 4; i++) {
            float e0 = __expf(s[i][0] + kb0);
            float e1 = __expf(s[i][1] + kb1);
            float e2 = __expf(s[i][2] + kb2);
            float e3 = __expf(s[i][3] + kb3);
            l_i[i] += e0 + e1 + e2 + e3;
            *(float4*)&Ps[(ty * 4 + i) * 68 + tx * 4] = make_float4(e0, e1, e2, e3);
        }
        __syncthreads();

#pragma unroll 4
        for (int k4 = 0; k4 < 16; k4++) {
            int k = k4 * 4;
            float4 b0 = *(float4*)&Vs[(k + 0) * 64 + tx * 4];
            float4 b1 = *(float4*)&Vs[(k + 1) * 64 + tx * 4];
            float4 b2 = *(float4*)&Vs[(k + 2) * 64 + tx * 4];
            float4 b3 = *(float4*)&Vs[(k + 3) * 64 + tx * 4];
#pragma unroll
            for (int i = 0; i < 4; i++) {
                float4 a = *(float4*)&Ps[(ty * 4 + i) * 68 + k];
                o[i][0] += a.x * b0.x + a.y * b1.x + a.z * b2.x + a.w * b3.x;
                o[i][1] += a.x * b0.y + a.y * b1.y + a.z * b2.y + a.w * b3.y;
                o[i][2] += a.x * b0.z + a.y * b1.z + a.z * b2.z + a.w * b3.z;
                o[i][3] += a.x * b0.w + a.y * b1.w + a.z * b2.w + a.w * b3.w;
            }
        }
    }

#pragma unroll
    for (int i = 0; i < 4; i++) {
#pragma unroll
        for (int off = 8; off > 0; off >>= 1)
            l_i[i] += __shfl_xor_sync(0xffffffffu, l_i[i], off);
    }

    int b = bh >> 3, h = bh & 7;
    int c0 = h * 64 + tx * 4;
#pragma unroll
    for (int i = 0; i < 4; i++) {
        float inv = 1.0f / l_i[i];
        int m = b * NL + i0 + ty * 4 + i;
        __nv_bfloat16 hh[4], ll[4];
#pragma unroll
        for (int j = 0; j < 4; j++) bf16split(o[i][j] * inv, hh[j], ll[j]);
        uint32_t h01 = (uint32_t)__bfloat16_as_ushort(hh[0]) | ((uint32_t)__bfloat16_as_ushort(hh[1]) << 16);
        uint32_t h23 = (uint32_t)__bfloat16_as_ushort(hh[2]) | ((uint32_t)__bfloat16_as_ushort(hh[3]) << 16);
        uint32_t l01 = (uint32_t)__bfloat16_as_ushort(ll[0]) | ((uint32_t)__bfloat16_as_ushort(ll[1]) << 16);
        uint32_t l23 = (uint32_t)__bfloat16_as_ushort(ll[2]) | ((uint32_t)__bfloat16_as_ushort(ll[3]) << 16);
        size_t base = (size_t)m * GK;
        *(uint2*)&g_Oc[base + c0]        = make_uint2(h01, h23);
        *(uint2*)&g_Oc[base + 512 + c0]  = make_uint2(l01, l23);
        *(uint2*)&g_Oc[base + 1024 + c0] = make_uint2(h01, h23);
    }
}

// ---------------- launch -----------------------------------------------------
extern "C" void kernel_launch(void* const* d_in, const int* in_sizes, int n_in,
                              void* d_out, int out_size) {
    const float* features = (const float*)d_in[0];
    const float* ln_g = (const float*)d_in[2];
    const float* ln_b = (const float*)d_in[3];
    const float* wq  = (const float*)d_in[4];  const float* bq  = (const float*)d_in[5];
    const float* wk  = (const float*)d_in[6];  const float* bk  = (const float*)d_in[7];
    const float* wv  = (const float*)d_in[8];  const float* bv  = (const float*)d_in[9];
    const float* wqp = (const float*)d_in[10]; const float* bqp = (const float*)d_in[11];
    const float* wkp = (const float*)d_in[12]; const float* bkp = (const float*)d_in[13];
    const float* wo  = (const float*)d_in[16]; const float* bo  = (const float*)d_in[17];
    const float* pscale = (const float*)d_in[18];
    float* out = (float*)d_out;

    cudaFuncSetAttribute(flash_kernel, cudaFuncAttributeMaxDynamicSharedMemorySize, FLASH_SMEM);

    int packT = NCOLP * NC + NC * NC;
    pack_kernel<<<(packT + 255) / 256, 256>>>(wq, wk, wv, wqp, wkp,
                                              bq, bk, bv, bqp, bkp, wo, pscale);
    ln_kernel<<<NM, 256>>>(features, ln_g, ln_b);
    zero_pads_kernel<<<(2 * NBH * NL + 255) / 256, 256>>>();
    gemm_mma<0><<<dim3(NCOLP / 128, NM / 128), 256>>>(nullptr, nullptr);
    kbias_kernel<<<(NBH * NL + 255) / 256, 256>>>(pscale);
    flash_kernel<<<dim3(NL / 64, NBH), 256, FLASH_SMEM>>>();
    gemm_mma<1><<<dim3(NC / 128, NM / 128), 256>>>(bo, out);
}

// round 5
// speedup vs baseline: 1.6982x; 1.5983x over previous
#include <cuda_runtime.h>
#include <cuda_bf16.h>
#include <cstdint>
#include <stdint.h>

// ---------------- problem constants -----------------------------------------
#define NB   2
#define NL   1024
#define NC   512
#define NH   8
#define ND   64
#define NDE  80
#define NCOL 1728
#define NCOLP 1792
#define NM   2048
#define NBH  16
#define GK   1536        // split-concat K' = 3*512

// ---------------- scratch ----------------------------------------------------
__device__ float g_Q[NBH * NL * NDE];          // q_ext fp32 (dims 0..75 valid)
__device__ float g_K[NBH * NL * NDE];
__device__ float g_V[NBH * NL * ND];
__device__ float g_kb[NBH * NL];
__device__ float g_bias[NCOL];
__device__ __nv_bfloat16 g_xc[NM * GK];        // LN(x) [hi,lo,hi]
__device__ __nv_bfloat16 g_Wc[NCOLP * GK];     // packed W^T [hi,hi,lo]
__device__ __nv_bfloat16 g_Oc[NM * GK];        // attn out [hi,lo,hi]
__device__ __nv_bfloat16 g_WoC[NC * GK];       // wo^T [hi,hi,lo]
__device__ __nv_bfloat16 g_Qc[NBH * NL * 160]; // q_ext bf16 [hi(80)|lo(80)]
__device__ __nv_bfloat16 g_Kc[NBH * NL * 160];

__device__ __forceinline__ void bf16split(float v, __nv_bfloat16& hi, __nv_bfloat16& lo) {
    hi = __float2bfloat16(v);
    lo = __float2bfloat16(v - __bfloat162float(hi));
}
__device__ __forceinline__ uint32_t pk2(__nv_bfloat16 a, __nv_bfloat16 b) {
    return (uint32_t)__bfloat16_as_ushort(a) | ((uint32_t)__bfloat16_as_ushort(b) << 16);
}
__device__ __forceinline__ uint32_t smem_u32(const void* p) {
    uint32_t a;
    asm("{ .reg .u64 t; cvta.to.shared.u64 t, %1; cvt.u32.u64 %0, t; }" : "=r"(a) : "l"(p));
    return a;
}
__device__ __forceinline__ void mma16816(float* c, const uint32_t* a, const uint32_t* b) {
    asm volatile("mma.sync.aligned.m16n8k16.row.col.f32.bf16.bf16.f32 "
                 "{%0,%1,%2,%3}, {%4,%5,%6,%7}, {%8,%9}, {%0,%1,%2,%3};"
                 : "+f"(c[0]), "+f"(c[1]), "+f"(c[2]), "+f"(c[3])
                 : "r"(a[0]), "r"(a[1]), "r"(a[2]), "r"(a[3]), "r"(b[0]), "r"(b[1]));
}
__device__ __forceinline__ void cpa16(uint32_t dst, const void* src) {
    asm volatile("cp.async.ca.shared.global [%0], [%1], 16;" :: "r"(dst), "l"(src));
}
#define CP_COMMIT() asm volatile("cp.async.commit_group;")
#define CP_WAIT2()  asm volatile("cp.async.wait_group 2;")

// ---------------- 1) pack weights via 32x32 smem transpose -------------------
__global__ void __launch_bounds__(256) pack_w(const float* __restrict__ wq,
                                              const float* __restrict__ wk,
                                              const float* __restrict__ wv,
                                              const float* __restrict__ wqp,
                                              const float* __restrict__ wkp,
                                              const float* __restrict__ wo,
                                              const float* __restrict__ pscale) {
    __shared__ float smt[32][33];
    int tx = threadIdx.x & 31, ty = threadIdx.x >> 5;
    int k0 = blockIdx.x * 32;
    int nt = blockIdx.y;
    if (nt < 56) {
        int n0 = nt * 32;
        const float* src; int ld, col;
        if (n0 < 512)       { src = wq;  ld = 512; col = n0; }
        else if (n0 < 1024) { src = wk;  ld = 512; col = n0 - 512; }
        else if (n0 < 1536) { src = wv;  ld = 512; col = n0 - 1024; }
        else if (n0 < 1632) { src = wqp; ld = 96;  col = n0 - 1536; }
        else if (n0 < 1728) { src = wkp; ld = 96;  col = n0 - 1632; }
        else                { src = nullptr; ld = 0; col = 0; }
#pragma unroll
        for (int i = 0; i < 4; i++) {
            int kr = ty + i * 8;
            smt[kr][tx] = src ? src[(size_t)(k0 + kr) * ld + col + tx] : 0.f;
        }
        __syncthreads();
#pragma unroll
        for (int i = 0; i < 4; i++) {
            int n = n0 + ty + i * 8, k = k0 + tx;
            float v = smt[tx][ty + i * 8];
            if (n < 512) v *= 0.125f;
            else if (n >= 1536 && n < 1632) v *= 2.0f * pscale[(n - 1536) / 12];
            __nv_bfloat16 hi, lo; bf16split(v, hi, lo);
            g_Wc[(size_t)n * GK + k]        = hi;
            g_Wc[(size_t)n * GK + 512 + k]  = hi;
            g_Wc[(size_t)n * GK + 1024 + k] = lo;
        }
    } else {
        int n0 = (nt - 56) * 32;
#pragma unroll
        for (int i = 0; i < 4; i++) {
            int kr = ty + i * 8;
            smt[kr][tx] = wo[(size_t)(k0 + kr) * 512 + n0 + tx];
        }
        __syncthreads();
#pragma unroll
        for (int i = 0; i < 4; i++) {
            int n = n0 + ty + i * 8, k = k0 + tx;
            __nv_bfloat16 hi, lo; bf16split(smt[tx][ty + i * 8], hi, lo);
            g_WoC[(size_t)n * GK + k]        = hi;
            g_WoC[(size_t)n * GK + 512 + k]  = hi;
            g_WoC[(size_t)n * GK + 1024 + k] = lo;
        }
    }
}

__global__ void pack_bias(const float* __restrict__ bq, const float* __restrict__ bk,
                          const float* __restrict__ bv, const float* __restrict__ bqp,
                          const float* __restrict__ bkp, const float* __restrict__ pscale) {
    int n = blockIdx.x * 256 + threadIdx.x;
    if (n >= NCOL) return;
    float bb;
    if (n < 512)        bb = bq[n] * 0.125f;
    else if (n < 1024)  bb = bk[n - 512];
    else if (n < 1536)  bb = bv[n - 1024];
    else if (n < 1632) { int c = n - 1536; bb = bqp[c] * 2.0f * pscale[c / 12]; }
    else               { int c = n - 1632; bb = bkp[c]; }
    g_bias[n] = bb;
}

// ---------------- 2) LayerNorm -> split-concat bf16 -------------------------
__global__ void ln_kernel(const float* __restrict__ f, const float* __restrict__ g,
                          const float* __restrict__ bb) {
    int row = blockIdx.x, t = threadIdx.x;
    const float* xr = f + (size_t)row * NC;
    float v0 = xr[t], v1 = xr[t + 256];
    float s = v0 + v1, s2 = v0 * v0 + v1 * v1;
#pragma unroll
    for (int o = 16; o > 0; o >>= 1) {
        s  += __shfl_xor_sync(0xffffffffu, s, o);
        s2 += __shfl_xor_sync(0xffffffffu, s2, o);
    }
    __shared__ float sh[16];
    if ((t & 31) == 0) { sh[t >> 5] = s; sh[8 + (t >> 5)] = s2; }
    __syncthreads();
    float ts = 0.f, ts2 = 0.f;
#pragma unroll
    for (int i = 0; i < 8; i++) { ts += sh[i]; ts2 += sh[8 + i]; }
    float mu   = ts * (1.0f / NC);
    float var  = ts2 * (1.0f / NC) - mu * mu;
    float rstd = rsqrtf(var + 1e-5f);
    float x0 = (v0 - mu) * rstd * g[t] + bb[t];
    float x1 = (v1 - mu) * rstd * g[t + 256] + bb[t + 256];
    size_t base = (size_t)row * GK;
    __nv_bfloat16 h0, l0, h1, l1;
    bf16split(x0, h0, l0); bf16split(x1, h1, l1);
    g_xc[base + t]        = h0;  g_xc[base + t + 256]        = h1;
    g_xc[base + 512 + t]  = l0;  g_xc[base + 512 + t + 256]  = l1;
    g_xc[base + 1024 + t] = h0;  g_xc[base + 1024 + t + 256] = h1;
}

// ---------------- 3) cp.async 4-stage GEMM (128x128, K'=1536) ----------------
#define SROW 40
#define GEMM_SMEM 81920
template <int MODE>
__global__ void __launch_bounds__(256) gemm_cp(const float* __restrict__ bias2,
                                               float* __restrict__ outp) {
    extern __shared__ char gsm[];
    uint32_t smBase = smem_u32(gsm);
    int tid = threadIdx.x, lane = tid & 31, wid = tid >> 5;
    int wm = wid & 1, wn = wid >> 1;
    int m0 = blockIdx.y * 128, n0 = blockIdx.x * 128;
    const __nv_bfloat16* Ap = (MODE == 0 ? g_xc : g_Oc) + (size_t)m0 * GK;
    const __nv_bfloat16* Bp = (MODE == 0 ? g_Wc : g_WoC) + (size_t)n0 * GK;

    int lr0 = tid >> 2, lq = tid & 3;
    int lr1 = lr0 + 64;

#define GEMM_ISSUE(S) do {                                                            \
    int st_ = (S) & 3; int k0_ = (S) * 32;                                            \
    uint32_t aB = smBase + st_ * 10240;                                               \
    uint32_t bB = smBase + 40960 + st_ * 10240;                                       \
    cpa16(aB + (lr0 * SROW + lq * 8) * 2, Ap + (size_t)lr0 * GK + k0_ + lq * 8);      \
    cpa16(aB + (lr1 * SROW + lq * 8) * 2, Ap + (size_t)lr1 * GK + k0_ + lq * 8);      \
    cpa16(bB + (lr0 * SROW + lq * 8) * 2, Bp + (size_t)lr0 * GK + k0_ + lq * 8);      \
    cpa16(bB + (lr1 * SROW + lq * 8) * 2, Bp + (size_t)lr1 * GK + k0_ + lq * 8);      \
    CP_COMMIT();                                                                      \
} while (0)

    GEMM_ISSUE(0); GEMM_ISSUE(1); GEMM_ISSUE(2);

    float c[4][4][4];
#pragma unroll
    for (int i = 0; i < 4; i++)
#pragma unroll
        for (int j = 0; j < 4; j++)
#pragma unroll
            for (int e = 0; e < 4; e++) c[i][j][e] = 0.f;

    const int NS = GK / 32;   // 48
    for (int s = 0; s < NS; s++) {
        CP_WAIT2();
        __syncthreads();
        if (s + 3 < NS) GEMM_ISSUE(s + 3);
        int st = s & 3;
        const __nv_bfloat16* Asm = (const __nv_bfloat16*)(gsm + st * 10240);
        const __nv_bfloat16* Bsm = (const __nv_bfloat16*)(gsm + 40960 + st * 10240);
#pragma unroll
        for (int ks = 0; ks < 2; ks++) {
            int kk = ks * 16 + (lane & 3) * 2;
            uint32_t a[4][4], b[4][2];
#pragma unroll
            for (int mf = 0; mf < 4; mf++) {
                int r = wm * 64 + mf * 16 + (lane >> 2);
                a[mf][0] = *(const uint32_t*)&Asm[r * SROW + kk];
                a[mf][1] = *(const uint32_t*)&Asm[(r + 8) * SROW + kk];
                a[mf][2] = *(const uint32_t*)&Asm[r * SROW + kk + 8];
                a[mf][3] = *(const uint32_t*)&Asm[(r + 8) * SROW + kk + 8];
            }
#pragma unroll
            for (int nf = 0; nf < 4; nf++) {
                int nr = wn * 32 + nf * 8 + (lane >> 2);
                b[nf][0] = *(const uint32_t*)&Bsm[nr * SROW + kk];
                b[nf][1] = *(const uint32_t*)&Bsm[nr * SROW + kk + 8];
            }
#pragma unroll
            for (int mf = 0; mf < 4; mf++)
#pragma unroll
                for (int nf = 0; nf < 4; nf++)
                    mma16816(c[mf][nf], a[mf], b[nf]);
        }
    }
#undef GEMM_ISSUE

    // epilogue
#pragma unroll
    for (int mf = 0; mf < 4; mf++) {
#pragma unroll
        for (int nf = 0; nf < 4; nf++) {
#pragma unroll
            for (int e = 0; e < 4; e++) {
                int m = m0 + wm * 64 + mf * 16 + (lane >> 2) + ((e >> 1) << 3);
                int n = n0 + wn * 32 + nf * 8 + ((lane & 3) << 1) + (e & 1);
                float v = c[mf][nf][e];
                if (MODE == 0) {
                    if (n < NCOL) {
                        v += g_bias[n];
                        int b = m >> 10, l = m & 1023;
                        if (n < 512) {
                            int h = n >> 6, d = n & 63;
                            g_Q[(size_t)((b * 8 + h) * NL + l) * NDE + d] = v;
                        } else if (n < 1024) {
                            int n2 = n - 512; int h = n2 >> 6, d = n2 & 63;
                            g_K[(size_t)((b * 8 + h) * NL + l) * NDE + d] = v;
                        } else if (n < 1536) {
                            int n2 = n - 1024; int h = n2 >> 6, d = n2 & 63;
                            g_V[(size_t)((b * 8 + h) * NL + l) * ND + d] = v;
                        } else if (n < 1632) {
                            int cc = n - 1536; int h = cc / 12, r = cc - h * 12;
                            g_Q[(size_t)((b * 8 + h) * NL + l) * NDE + 64 + r] = v;
                        } else {
                            int cc = n - 1632; int h = cc / 12, r = cc - h * 12;
                            g_K[(size_t)((b * 8 + h) * NL + l) * NDE + 64 + r] = v;
                        }
                    }
                } else {
                    outp[(size_t)m * NC + n] = v + bias2[n];
                }
            }
        }
    }
}

// ---------------- 4) convert Q/K fp32 -> bf16 hi|lo (pads zeroed) -----------
__global__ void convert_qk() {
    int idx = blockIdx.x * 256 + threadIdx.x;
    if (idx >= NBH * NL * 80) return;
    int row = idx / 80, d = idx % 80;
    float q = (d < 76) ? g_Q[(size_t)row * NDE + d] : 0.f;
    float k = (d < 76) ? g_K[(size_t)row * NDE + d] : 0.f;
    __nv_bfloat16 qh, ql, kh, kl;
    bf16split(q, qh, ql); bf16split(k, kh, kl);
    size_t base = (size_t)row * 160;
    g_Qc[base + d] = qh;  g_Qc[base + 80 + d] = ql;
    g_Kc[base + d] = kh;  g_Kc[base + 80 + d] = kl;
}

// ---------------- 5) key bias -----------------------------------------------
__global__ void kbias_kernel(const float* __restrict__ pscale) {
    int row = blockIdx.x * blockDim.x + threadIdx.x;
    if (row >= NBH * NL) return;
    int h = (row >> 10) & 7;
    const float* kp = &g_K[(size_t)row * NDE + 64];
    float s = 0.f;
#pragma unroll
    for (int r = 0; r < 12; r++) { float v = kp[r]; s += v * v; }
    g_kb[row] = -pscale[h] * s;
}

// ---------------- 6) flash attention on tensor cores -------------------------
// CTA: 64 q-rows, 128 threads (4 warps x 16q). K-tiles of 64 keys.
// smem bytes: Qs 64x168bf16=21504 | Ks 21504 | VhT 64x72=9216 | VlT 9216 | kbs 256
#define FQ_B  0
#define FK_B  21504
#define FVH_B 43008
#define FVL_B 52224
#define FKB_B 61440
#define FLASH_SMEM 61696

__global__ void __launch_bounds__(128) flash_tc() {
    extern __shared__ char fsm[];
    __nv_bfloat16* Qs = (__nv_bfloat16*)(fsm + FQ_B);
    __nv_bfloat16* Ks = (__nv_bfloat16*)(fsm + FK_B);
    uint32_t* Qs32 = (uint32_t*)Qs;
    uint32_t* Ks32 = (uint32_t*)Ks;
    uint32_t* VhT = (uint32_t*)(fsm + FVH_B);   // [d][36 words], keys packed 2/word
    uint32_t* VlT = (uint32_t*)(fsm + FVL_B);
    float* kbs = (float*)(fsm + FKB_B);

    int tid = threadIdx.x, lane = tid & 31, wid = tid >> 5;
    int bh = blockIdx.y, i0 = blockIdx.x << 6;

    const __nv_bfloat16* Qg = g_Qc + (size_t)(bh * NL + i0) * 160;
    const __nv_bfloat16* Kg0 = g_Kc + (size_t)(bh * NL) * 160;
    const float* Vg0 = g_V + (size_t)(bh * NL) * 64;

    // load Q tile once: 64 rows x 160 bf16 -> padded stride 168
    for (int idx = tid; idx < 64 * 20; idx += 128) {
        int row = idx / 20, ch = idx % 20;
        *(uint4*)&Qs[row * 168 + ch * 8] = *(const uint4*)(Qg + row * 160 + ch * 8);
    }

    float oc[8][4];
#pragma unroll
    for (int i = 0; i < 8; i++)
#pragma unroll
        for (int e = 0; e < 4; e++) oc[i][e] = 0.f;
    float l_i[2] = {0.f, 0.f};

    int qr = (lane >> 2);            // fragment row within warp tile
    int lm4 = lane & 3;

    for (int kt = 0; kt < 16; kt++) {
        __syncthreads();
        int j0 = kt << 6;
        // K tile: 64 keys x 160 bf16
        const __nv_bfloat16* Kg = Kg0 + (size_t)j0 * 160;
        for (int idx = tid; idx < 64 * 20; idx += 128) {
            int row = idx / 20, ch = idx % 20;
            *(uint4*)&Ks[row * 168 + ch * 8] = *(const uint4*)(Kg + row * 160 + ch * 8);
        }
        // V tile: split + transpose into VhT/VlT [d][keypair words]
        const float* Vg = Vg0 + (size_t)j0 * 64;
#pragma unroll
        for (int i = 0; i < 4; i++) {
            int cid = tid + i * 128;               // 512 chunks
            int kp = cid >> 4, d0 = (cid & 15) << 2;
            float4 a = *(const float4*)(Vg + (size_t)(2 * kp) * 64 + d0);
            float4 b = *(const float4*)(Vg + (size_t)(2 * kp + 1) * 64 + d0);
            float av[4] = {a.x, a.y, a.z, a.w};
            float bv[4] = {b.x, b.y, b.z, b.w};
#pragma unroll
            for (int j = 0; j < 4; j++) {
                __nv_bfloat16 ah, al, bh_, bl;
                bf16split(av[j], ah, al);
                bf16split(bv[j], bh_, bl);
                VhT[(d0 + j) * 36 + kp] = pk2(ah, bh_);
                VlT[(d0 + j) * 36 + kp] = pk2(al, bl);
            }
        }
        if (tid < 64) kbs[tid] = g_kb[bh * NL + j0 + tid];
        __syncthreads();

        // ---- S = Q_ext . K_ext^T via 3 phases (hi*hi, lo*hi, hi*lo) ----
        float sc[8][4];
#pragma unroll
        for (int i = 0; i < 8; i++)
#pragma unroll
            for (int e = 0; e < 4; e++) sc[i][e] = 0.f;

#pragma unroll
        for (int ph = 0; ph < 3; ph++) {
            int qoff = (ph == 1) ? 80 : 0;
            int koff = (ph == 2) ? 80 : 0;
#pragma unroll
            for (int ks = 0; ks < 5; ks++) {
                int dq = qoff + ks * 16 + 2 * lm4;
                int arow = wid * 16 + qr;
                uint32_t a[4];
                a[0] = Qs32[arow * 84 + (dq >> 1)];
                a[1] = Qs32[(arow + 8) * 84 + (dq >> 1)];
                a[2] = Qs32[arow * 84 + ((dq + 8) >> 1)];
                a[3] = Qs32[(arow + 8) * 84 + ((dq + 8) >> 1)];
                int dk = koff + ks * 16 + 2 * lm4;
#pragma unroll
                for (int nf = 0; nf < 8; nf++) {
                    int key = nf * 8 + qr;
                    uint32_t b[2];
                    b[0] = Ks32[key * 84 + (dk >> 1)];
                    b[1] = Ks32[key * 84 + ((dk + 8) >> 1)];
                    mma16816(sc[nf], a, b);
                }
            }
        }

        // ---- bias + exp + pack P (in-register), accumulate l ----
        uint32_t ph_[8][2], pl_[8][2];
#pragma unroll
        for (int nf = 0; nf < 8; nf++) {
            int k0 = nf * 8 + 2 * lm4;
            float kb0 = kbs[k0], kb1 = kbs[k0 + 1];
            float e0 = __expf(sc[nf][0] + kb0);
            float e1 = __expf(sc[nf][1] + kb1);
            float e2 = __expf(sc[nf][2] + kb0);
            float e3 = __expf(sc[nf][3] + kb1);
            l_i[0] += e0 + e1;
            l_i[1] += e2 + e3;
            __nv_bfloat16 h0, l0, h1, l1, h2, l2, h3, l3;
            bf16split(e0, h0, l0); bf16split(e1, h1, l1);
            bf16split(e2, h2, l2); bf16split(e3, h3, l3);
            ph_[nf][0] = pk2(h0, h1); ph_[nf][1] = pk2(h2, h3);
            pl_[nf][0] = pk2(l0, l1); pl_[nf][1] = pk2(l2, l3);
        }

        // ---- O += P.V via 3 phases (Ph*Vh, Pl*Vh, Ph*Vl) ----
#pragma unroll
        for (int pv = 0; pv < 3; pv++) {
            uint32_t* VT = (pv == 2) ? VlT : VhT;
#pragma unroll
            for (int t = 0; t < 4; t++) {
                uint32_t a[4];
                if (pv == 1) {
                    a[0] = pl_[2 * t][0]; a[1] = pl_[2 * t][1];
                    a[2] = pl_[2 * t + 1][0]; a[3] = pl_[2 * t + 1][1];
                } else {
                    a[0] = ph_[2 * t][0]; a[1] = ph_[2 * t][1];
                    a[2] = ph_[2 * t + 1][0]; a[3] = ph_[2 * t + 1][1];
                }
                int kw = t * 8 + lm4;
#pragma unroll
                for (int nfv = 0; nfv < 8; nfv++) {
                    int d = nfv * 8 + qr;
                    uint32_t b[2];
                    b[0] = VT[d * 36 + kw];
                    b[1] = VT[d * 36 + kw + 4];
                    mma16816(oc[nfv], a, b);
                }
            }
        }
    }

    // reduce row sums across the 4 lanes sharing each row
    l_i[0] += __shfl_xor_sync(0xffffffffu, l_i[0], 1);
    l_i[0] += __shfl_xor_sync(0xffffffffu, l_i[0], 2);
    l_i[1] += __shfl_xor_sync(0xffffffffu, l_i[1], 1);
    l_i[1] += __shfl_xor_sync(0xffffffffu, l_i[1], 2);
    float inv0 = 1.0f / l_i[0], inv1 = 1.0f / l_i[1];

    // write O (normalized) as split-concat bf16 rows of g_Oc
    int b = bh >> 3, h = bh & 7;
    int l0r = i0 + wid * 16 + qr;
    size_t base0 = (size_t)(b * NL + l0r) * GK;
    size_t base1 = (size_t)(b * NL + l0r + 8) * GK;
#pragma unroll
    for (int nfv = 0; nfv < 8; nfv++) {
        int col = h * 64 + nfv * 8 + 2 * lm4;
        float v0 = oc[nfv][0] * inv0, v1 = oc[nfv][1] * inv0;
        float w0 = oc[nfv][2] * inv1, w1 = oc[nfv][3] * inv1;
        __nv_bfloat16 vh0, vl0, vh1, vl1, wh0, wl0, wh1, wl1;
        bf16split(v0, vh0, vl0); bf16split(v1, vh1, vl1);
        bf16split(w0, wh0, wl0); bf16split(w1, wh1, wl1);
        *(uint32_t*)&g_Oc[base0 + col]        = pk2(vh0, vh1);
        *(uint32_t*)&g_Oc[base0 + 512 + col]  = pk2(vl0, vl1);
        *(uint32_t*)&g_Oc[base0 + 1024 + col] = pk2(vh0, vh1);
        *(uint32_t*)&g_Oc[base1 + col]        = pk2(wh0, wh1);
        *(uint32_t*)&g_Oc[base1 + 512 + col]  = pk2(wl0, wl1);
        *(uint32_t*)&g_Oc[base1 + 1024 + col] = pk2(wh0, wh1);
    }
}

// ---------------- launch -----------------------------------------------------
extern "C" void kernel_launch(void* const* d_in, const int* in_sizes, int n_in,
                              void* d_out, int out_size) {
    const float* features = (const float*)d_in[0];
    const float* ln_g = (const float*)d_in[2];
    const float* ln_b = (const float*)d_in[3];
    const float* wq  = (const float*)d_in[4];  const float* bq  = (const float*)d_in[5];
    const float* wk  = (const float*)d_in[6];  const float* bk  = (const float*)d_in[7];
    const float* wv  = (const float*)d_in[8];  const float* bv  = (const float*)d_in[9];
    const float* wqp = (const float*)d_in[10]; const float* bqp = (const float*)d_in[11];
    const float* wkp = (const float*)d_in[12]; const float* bkp = (const float*)d_in[13];
    const float* wo  = (const float*)d_in[16]; const float* bo  = (const float*)d_in[17];
    const float* pscale = (const float*)d_in[18];
    float* out = (float*)d_out;

    cudaFuncSetAttribute(gemm_cp<0>, cudaFuncAttributeMaxDynamicSharedMemorySize, GEMM_SMEM);
    cudaFuncSetAttribute(gemm_cp<1>, cudaFuncAttributeMaxDynamicSharedMemorySize, GEMM_SMEM);
    cudaFuncSetAttribute(flash_tc, cudaFuncAttributeMaxDynamicSharedMemorySize, FLASH_SMEM);

    pack_w<<<dim3(16, 72), 256>>>(wq, wk, wv, wqp, wkp, wo, pscale);
    pack_bias<<<7, 256>>>(bq, bk, bv, bqp, bkp, pscale);
    ln_kernel<<<NM, 256>>>(features, ln_g, ln_b);
    gemm_cp<0><<<dim3(NCOLP / 128, NM / 128), 256, GEMM_SMEM>>>(nullptr, nullptr);
    convert_qk<<<(NBH * NL * 80 + 255) / 256, 256>>>();
    kbias_kernel<<<(NBH * NL + 255) / 256, 256>>>(pscale);
    flash_tc<<<dim3(NL / 64, NBH), 128, FLASH_SMEM>>>();
    gemm_cp<1><<<dim3(NC / 128, NM / 128), 256, GEMM_SMEM>>>(bo, out);
}

// round 6
// speedup vs baseline: 1.9345x; 1.1391x over previous
#include <cuda_runtime.h>
#include <cuda_bf16.h>
#include <cstdint>
#include <stdint.h>

// ---------------- problem constants -----------------------------------------
#define NL   1024
#define NC   512
#define NCOL 1728
#define NCOLP 1792
#define NM   2048
#define NBH  16
#define GK   1536        // split-concat K' = 3*512

// ---------------- scratch ----------------------------------------------------
__device__ float g_V[NBH * NL * 64];
__device__ float g_Kp[NBH * NL * 12];          // k point dims fp32 (for kbias)
__device__ float g_kb[NBH * NL];
__device__ float g_bias[NCOL];
__device__ __nv_bfloat16 g_xc[NM * GK];        // LN(x) [hi,lo,hi]
__device__ __nv_bfloat16 g_Wc[NCOLP * GK];     // packed W^T [hi,hi,lo]
__device__ __nv_bfloat16 g_Oc[NM * GK];        // attn out [hi,lo,hi]
__device__ __nv_bfloat16 g_WoC[NC * GK];       // wo^T [hi,hi,lo]
__device__ __nv_bfloat16 g_Qc[NBH * NL * 160]; // q_ext bf16 [hi(80)|lo(80)]; pads stay 0
__device__ __nv_bfloat16 g_Kc[NBH * NL * 160];

__device__ __forceinline__ void bf16split(float v, __nv_bfloat16& hi, __nv_bfloat16& lo) {
    hi = __float2bfloat16(v);
    lo = __float2bfloat16(v - __bfloat162float(hi));
}
__device__ __forceinline__ uint32_t pk2(__nv_bfloat16 a, __nv_bfloat16 b) {
    return (uint32_t)__bfloat16_as_ushort(a) | ((uint32_t)__bfloat16_as_ushort(b) << 16);
}
__device__ __forceinline__ uint32_t smem_u32(const void* p) {
    uint32_t a;
    asm("{ .reg .u64 t; cvta.to.shared.u64 t, %1; cvt.u32.u64 %0, t; }" : "=r"(a) : "l"(p));
    return a;
}
__device__ __forceinline__ void mma16816(float* c, const uint32_t* a, const uint32_t* b) {
    asm volatile("mma.sync.aligned.m16n8k16.row.col.f32.bf16.bf16.f32 "
                 "{%0,%1,%2,%3}, {%4,%5,%6,%7}, {%8,%9}, {%0,%1,%2,%3};"
                 : "+f"(c[0]), "+f"(c[1]), "+f"(c[2]), "+f"(c[3])
                 : "r"(a[0]), "r"(a[1]), "r"(a[2]), "r"(a[3]), "r"(b[0]), "r"(b[1]));
}
__device__ __forceinline__ void cpa16(uint32_t dst, const void* src) {
    asm volatile("cp.async.ca.shared.global [%0], [%1], 16;" :: "r"(dst), "l"(src));
}
#define CP_COMMIT() asm volatile("cp.async.commit_group;")
#define CP_WAIT2()  asm volatile("cp.async.wait_group 2;")
#define LDMX4(r0, r1, r2, r3, addr)                                                   \
    asm volatile("ldmatrix.sync.aligned.m8n8.x4.shared.b16 {%0,%1,%2,%3}, [%4];"      \
                 : "=r"(r0), "=r"(r1), "=r"(r2), "=r"(r3) : "r"(addr))

// ---------------- 1) pack weights via 32x32 smem transpose -------------------
__global__ void __launch_bounds__(256) pack_w(const float* __restrict__ wq,
                                              const float* __restrict__ wk,
                                              const float* __restrict__ wv,
                                              const float* __restrict__ wqp,
                                              const float* __restrict__ wkp,
                                              const float* __restrict__ wo,
                                              const float* __restrict__ pscale) {
    __shared__ float smt[32][33];
    int tx = threadIdx.x & 31, ty = threadIdx.x >> 5;
    int k0 = blockIdx.x * 32;
    int nt = blockIdx.y;
    if (nt < 56) {
        int n0 = nt * 32;
        const float* src; int ld, col;
        if (n0 < 512)       { src = wq;  ld = 512; col = n0; }
        else if (n0 < 1024) { src = wk;  ld = 512; col = n0 - 512; }
        else if (n0 < 1536) { src = wv;  ld = 512; col = n0 - 1024; }
        else if (n0 < 1632) { src = wqp; ld = 96;  col = n0 - 1536; }
        else if (n0 < 1728) { src = wkp; ld = 96;  col = n0 - 1632; }
        else                { src = nullptr; ld = 0; col = 0; }
#pragma unroll
        for (int i = 0; i < 4; i++) {
            int kr = ty + i * 8;
            smt[kr][tx] = src ? src[(size_t)(k0 + kr) * ld + col + tx] : 0.f;
        }
        __syncthreads();
#pragma unroll
        for (int i = 0; i < 4; i++) {
            int n = n0 + ty + i * 8, k = k0 + tx;
            float v = smt[tx][ty + i * 8];
            if (n < 512) v *= 0.125f;
            else if (n >= 1536 && n < 1632) v *= 2.0f * pscale[(n - 1536) / 12];
            __nv_bfloat16 hi, lo; bf16split(v, hi, lo);
            g_Wc[(size_t)n * GK + k]        = hi;
            g_Wc[(size_t)n * GK + 512 + k]  = hi;
            g_Wc[(size_t)n * GK + 1024 + k] = lo;
        }
    } else {
        int n0 = (nt - 56) * 32;
#pragma unroll
        for (int i = 0; i < 4; i++) {
            int kr = ty + i * 8;
            smt[kr][tx] = wo[(size_t)(k0 + kr) * 512 + n0 + tx];
        }
        __syncthreads();
#pragma unroll
        for (int i = 0; i < 4; i++) {
            int n = n0 + ty + i * 8, k = k0 + tx;
            __nv_bfloat16 hi, lo; bf16split(smt[tx][ty + i * 8], hi, lo);
            g_WoC[(size_t)n * GK + k]        = hi;
            g_WoC[(size_t)n * GK + 512 + k]  = hi;
            g_WoC[(size_t)n * GK + 1024 + k] = lo;
        }
    }
}

__global__ void pack_bias(const float* __restrict__ bq, const float* __restrict__ bk,
                          const float* __restrict__ bv, const float* __restrict__ bqp,
                          const float* __restrict__ bkp, const float* __restrict__ pscale) {
    int n = blockIdx.x * 256 + threadIdx.x;
    if (n >= NCOL) return;
    float bb;
    if (n < 512)        bb = bq[n] * 0.125f;
    else if (n < 1024)  bb = bk[n - 512];
    else if (n < 1536)  bb = bv[n - 1024];
    else if (n < 1632) { int c = n - 1536; bb = bqp[c] * 2.0f * pscale[c / 12]; }
    else               { int c = n - 1632; bb = bkp[c]; }
    g_bias[n] = bb;
}

// ---------------- 2) LayerNorm -> split-concat bf16 -------------------------
__global__ void ln_kernel(const float* __restrict__ f, const float* __restrict__ g,
                          const float* __restrict__ bb) {
    int row = blockIdx.x, t = threadIdx.x;
    const float* xr = f + (size_t)row * NC;
    float v0 = xr[t], v1 = xr[t + 256];
    float s = v0 + v1, s2 = v0 * v0 + v1 * v1;
#pragma unroll
    for (int o = 16; o > 0; o >>= 1) {
        s  += __shfl_xor_sync(0xffffffffu, s, o);
        s2 += __shfl_xor_sync(0xffffffffu, s2, o);
    }
    __shared__ float sh[16];
    if ((t & 31) == 0) { sh[t >> 5] = s; sh[8 + (t >> 5)] = s2; }
    __syncthreads();
    float ts = 0.f, ts2 = 0.f;
#pragma unroll
    for (int i = 0; i < 8; i++) { ts += sh[i]; ts2 += sh[8 + i]; }
    float mu   = ts * (1.0f / NC);
    float var  = ts2 * (1.0f / NC) - mu * mu;
    float rstd = rsqrtf(var + 1e-5f);
    float x0 = (v0 - mu) * rstd * g[t] + bb[t];
    float x1 = (v1 - mu) * rstd * g[t + 256] + bb[t + 256];
    size_t base = (size_t)row * GK;
    __nv_bfloat16 h0, l0, h1, l1;
    bf16split(x0, h0, l0); bf16split(x1, h1, l1);
    g_xc[base + t]        = h0;  g_xc[base + t + 256]        = h1;
    g_xc[base + 512 + t]  = l0;  g_xc[base + 512 + t + 256]  = l1;
    g_xc[base + 1024 + t] = h0;  g_xc[base + 1024 + t + 256] = h1;
}

// ---------------- 3) GEMM: ldmatrix + BK=64, 4-stage cp.async ----------------
// 128x128 tile, 256 thr = 8 warps (2m x 4n), warp tile 64x32.
// stage smem: A 128x72 bf16 (18432 B) + B same -> 36864 B; 4 stages = 147456 B.
#define GEMM_SMEM 147456
template <int MODE>
__global__ void __launch_bounds__(256) gemm_cp(const float* __restrict__ bias2,
                                               float* __restrict__ outp) {
    extern __shared__ char gsm[];
    uint32_t smBase = smem_u32(gsm);
    int tid = threadIdx.x, lane = tid & 31, wid = tid >> 5;
    int wm = wid & 1, wn = wid >> 1;
    int l16 = lane & 15, lh = lane >> 4;
    int m0 = blockIdx.y * 128, n0 = blockIdx.x * 128;
    const __nv_bfloat16* Ap = (MODE == 0 ? g_xc : g_Oc) + (size_t)m0 * GK;
    const __nv_bfloat16* Bp = (MODE == 0 ? g_Wc : g_WoC) + (size_t)n0 * GK;

#define GEMM_ISSUE(S) do {                                                         \
    int st_ = (S) & 3; int k0_ = (S) * 64;                                         \
    uint32_t base_ = smBase + st_ * 36864;                                         \
    _Pragma("unroll")                                                              \
    for (int i_ = 0; i_ < 4; i_++) {                                               \
        int idx_ = tid + i_ * 256;                                                 \
        int row_ = idx_ >> 3, ch_ = idx_ & 7;                                      \
        cpa16(base_ + row_ * 144 + ch_ * 16, Ap + (size_t)row_ * GK + k0_ + ch_ * 8); \
        cpa16(base_ + 18432 + row_ * 144 + ch_ * 16, Bp + (size_t)row_ * GK + k0_ + ch_ * 8); \
    }                                                                              \
    CP_COMMIT();                                                                   \
} while (0)

    GEMM_ISSUE(0); GEMM_ISSUE(1); GEMM_ISSUE(2);

    float c[4][4][4];
#pragma unroll
    for (int i = 0; i < 4; i++)
#pragma unroll
        for (int j = 0; j < 4; j++)
#pragma unroll
            for (int e = 0; e < 4; e++) c[i][j][e] = 0.f;

    const int NS = GK / 64;   // 24
    for (int s = 0; s < NS; s++) {
        CP_WAIT2();
        __syncthreads();
        if (s + 3 < NS) GEMM_ISSUE(s + 3);
        uint32_t aB = smBase + (s & 3) * 36864;
        uint32_t bB = aB + 18432;
        uint32_t a_ad = aB + (wm * 64 + l16) * 144 + lh * 16;
        uint32_t b_ad = bB + (wn * 32 + l16) * 144 + lh * 16;
#pragma unroll
        for (int ks = 0; ks < 4; ks++) {
            uint32_t a[4][4], bb[2][4];
#pragma unroll
            for (int mf = 0; mf < 4; mf++)
                LDMX4(a[mf][0], a[mf][1], a[mf][2], a[mf][3], a_ad + mf * 2304 + ks * 32);
#pragma unroll
            for (int nfp = 0; nfp < 2; nfp++)
                LDMX4(bb[nfp][0], bb[nfp][1], bb[nfp][2], bb[nfp][3], b_ad + nfp * 2304 + ks * 32);
#pragma unroll
            for (int mf = 0; mf < 4; mf++)
#pragma unroll
                for (int nfp = 0; nfp < 2; nfp++) {
                    uint32_t be[2] = { bb[nfp][0], bb[nfp][2] };
                    uint32_t bo[2] = { bb[nfp][1], bb[nfp][3] };
                    mma16816(c[mf][2 * nfp],     a[mf], be);
                    mma16816(c[mf][2 * nfp + 1], a[mf], bo);
                }
        }
    }
#undef GEMM_ISSUE

    // epilogue: e-pairs (adjacent n) written as 32-bit / 64-bit stores
#pragma unroll
    for (int mf = 0; mf < 4; mf++) {
#pragma unroll
        for (int nf = 0; nf < 4; nf++) {
#pragma unroll
            for (int ep = 0; ep < 2; ep++) {
                int m = m0 + wm * 64 + mf * 16 + (lane >> 2) + ep * 8;
                int n = n0 + wn * 32 + nf * 8 + (lane & 3) * 2;
                float v0 = c[mf][nf][ep * 2 + 0];
                float v1 = c[mf][nf][ep * 2 + 1];
                if (MODE == 0) {
                    if (n < NCOL) {
                        v0 += g_bias[n]; v1 += g_bias[n + 1];
                        int b = m >> 10, l = m & 1023;
                        __nv_bfloat16 h0, lo0, h1, lo1;
                        bf16split(v0, h0, lo0); bf16split(v1, h1, lo1);
                        if (n < 512) {
                            int h = n >> 6, d = n & 63;
                            size_t row = (size_t)((b * 8 + h) * NL + l) * 160;
                            *(uint32_t*)&g_Qc[row + d]      = pk2(h0, h1);
                            *(uint32_t*)&g_Qc[row + 80 + d] = pk2(lo0, lo1);
                        } else if (n < 1024) {
                            int n2 = n - 512; int h = n2 >> 6, d = n2 & 63;
                            size_t row = (size_t)((b * 8 + h) * NL + l) * 160;
                            *(uint32_t*)&g_Kc[row + d]      = pk2(h0, h1);
                            *(uint32_t*)&g_Kc[row + 80 + d] = pk2(lo0, lo1);
                        } else if (n < 1536) {
                            int n2 = n - 1024; int h = n2 >> 6, d = n2 & 63;
                            size_t row = (size_t)((b * 8 + h) * NL + l);
                            *(float2*)&g_V[row * 64 + d] = make_float2(v0, v1);
                        } else if (n < 1632) {
                            int cc = n - 1536; int h = cc / 12, r = cc - h * 12;
                            size_t row = (size_t)((b * 8 + h) * NL + l) * 160;
                            *(uint32_t*)&g_Qc[row + 64 + r]  = pk2(h0, h1);
                            *(uint32_t*)&g_Qc[row + 144 + r] = pk2(lo0, lo1);
                        } else {
                            int cc = n - 1632; int h = cc / 12, r = cc - h * 12;
                            size_t row = (size_t)((b * 8 + h) * NL + l);
                            *(uint32_t*)&g_Kc[row * 160 + 64 + r]  = pk2(h0, h1);
                            *(uint32_t*)&g_Kc[row * 160 + 144 + r] = pk2(lo0, lo1);
                            *(float2*)&g_Kp[row * 12 + r] = make_float2(v0, v1);
                        }
                    }
                } else {
                    *(float2*)&outp[(size_t)m * NC + n] =
                        make_float2(v0 + bias2[n], v1 + bias2[n + 1]);
                }
            }
        }
    }
}

// ---------------- 4) key bias -----------------------------------------------
__global__ void kbias_kernel(const float* __restrict__ pscale) {
    int row = blockIdx.x * blockDim.x + threadIdx.x;
    if (row >= NBH * NL) return;
    int h = (row >> 10) & 7;
    float s = 0.f;
#pragma unroll
    for (int r = 0; r < 12; r++) { float v = g_Kp[row * 12 + r]; s += v * v; }
    g_kb[row] = -pscale[h] * s;
}

// ---------------- 5) flash attention on tensor cores (ldmatrix) -------------
#define FQ_B  0
#define FK_B  21504
#define FVH_B 43008
#define FVL_B 52224
#define FKB_B 61440
#define FLASH_SMEM 61696

__global__ void __launch_bounds__(128) flash_tc() {
    extern __shared__ char fsm[];
    __nv_bfloat16* Qs = (__nv_bfloat16*)(fsm + FQ_B);
    __nv_bfloat16* Ks = (__nv_bfloat16*)(fsm + FK_B);
    uint32_t* VhT = (uint32_t*)(fsm + FVH_B);   // [d][36 words], key pairs
    uint32_t* VlT = (uint32_t*)(fsm + FVL_B);
    float* kbs = (float*)(fsm + FKB_B);
    uint32_t sm = smem_u32(fsm);

    int tid = threadIdx.x, lane = tid & 31, wid = tid >> 5;
    int l16 = lane & 15, lh = lane >> 4;
    int bh = blockIdx.y, i0 = blockIdx.x << 6;

    const __nv_bfloat16* Qg = g_Qc + (size_t)(bh * NL + i0) * 160;
    const __nv_bfloat16* Kg0 = g_Kc + (size_t)(bh * NL) * 160;
    const float* Vg0 = g_V + (size_t)(bh * NL) * 64;

    // ldmatrix base addresses (per-lane)
    uint32_t qa_base = sm + FQ_B + (wid * 16 + l16) * 336 + lh * 16;
    uint32_t kb_base = sm + FK_B + l16 * 336 + lh * 16;
    uint32_t vh_base = sm + FVH_B + l16 * 144 + lh * 16;
    uint32_t vl_base = sm + FVL_B + l16 * 144 + lh * 16;

    for (int idx = tid; idx < 64 * 20; idx += 128) {
        int row = idx / 20, ch = idx % 20;
        *(uint4*)&Qs[row * 168 + ch * 8] = *(const uint4*)(Qg + row * 160 + ch * 8);
    }

    float oc[8][4];
#pragma unroll
    for (int i = 0; i < 8; i++)
#pragma unroll
        for (int e = 0; e < 4; e++) oc[i][e] = 0.f;
    float l_i[2] = {0.f, 0.f};
    int qr = lane >> 2, lm4 = lane & 3;

    for (int kt = 0; kt < 16; kt++) {
        __syncthreads();
        int j0 = kt << 6;
        const __nv_bfloat16* Kg = Kg0 + (size_t)j0 * 160;
        for (int idx = tid; idx < 64 * 20; idx += 128) {
            int row = idx / 20, ch = idx % 20;
            *(uint4*)&Ks[row * 168 + ch * 8] = *(const uint4*)(Kg + row * 160 + ch * 8);
        }
        const float* Vg = Vg0 + (size_t)j0 * 64;
#pragma unroll
        for (int i = 0; i < 4; i++) {
            int cid = tid + i * 128;
            int kp = cid >> 4, d0 = (cid & 15) << 2;
            float4 a = *(const float4*)(Vg + (size_t)(2 * kp) * 64 + d0);
            float4 b = *(const float4*)(Vg + (size_t)(2 * kp + 1) * 64 + d0);
            float av[4] = {a.x, a.y, a.z, a.w};
            float bv[4] = {b.x, b.y, b.z, b.w};
#pragma unroll
            for (int j = 0; j < 4; j++) {
                __nv_bfloat16 ah, al, bh_, bl;
                bf16split(av[j], ah, al);
                bf16split(bv[j], bh_, bl);
                VhT[(d0 + j) * 36 + kp] = pk2(ah, bh_);
                VlT[(d0 + j) * 36 + kp] = pk2(al, bl);
            }
        }
        if (tid < 64) kbs[tid] = g_kb[bh * NL + j0 + tid];
        __syncthreads();

        // ---- S = Q_ext . K_ext^T : 3 phases (hh, lh, hl) ----
        float sc[8][4];
#pragma unroll
        for (int i = 0; i < 8; i++)
#pragma unroll
            for (int e = 0; e < 4; e++) sc[i][e] = 0.f;

#pragma unroll
        for (int ph = 0; ph < 3; ph++) {
            uint32_t qoff = (ph == 1) ? 160u : 0u;   // bytes (80 bf16)
            uint32_t koff = (ph == 2) ? 160u : 0u;
#pragma unroll
            for (int ks = 0; ks < 5; ks++) {
                uint32_t a[4];
                LDMX4(a[0], a[1], a[2], a[3], qa_base + qoff + ks * 32);
#pragma unroll
                for (int nfp = 0; nfp < 4; nfp++) {
                    uint32_t b0, b1, b2, b3;
                    LDMX4(b0, b1, b2, b3, kb_base + nfp * 5376 + koff + ks * 32);
                    uint32_t be[2] = { b0, b2 };
                    uint32_t bo[2] = { b1, b3 };
                    mma16816(sc[2 * nfp],     a, be);
                    mma16816(sc[2 * nfp + 1], a, bo);
                }
            }
        }

        // ---- bias + exp + pack P in-register ----
        uint32_t ph_[8][2], pl_[8][2];
#pragma unroll
        for (int nf = 0; nf < 8; nf++) {
            int k0 = nf * 8 + 2 * lm4;
            float kb0 = kbs[k0], kb1 = kbs[k0 + 1];
            float e0 = __expf(sc[nf][0] + kb0);
            float e1 = __expf(sc[nf][1] + kb1);
            float e2 = __expf(sc[nf][2] + kb0);
            float e3 = __expf(sc[nf][3] + kb1);
            l_i[0] += e0 + e1;
            l_i[1] += e2 + e3;
            __nv_bfloat16 h0, l0, h1, l1, h2, l2, h3, l3;
            bf16split(e0, h0, l0); bf16split(e1, h1, l1);
            bf16split(e2, h2, l2); bf16split(e3, h3, l3);
            ph_[nf][0] = pk2(h0, h1); ph_[nf][1] = pk2(h2, h3);
            pl_[nf][0] = pk2(l0, l1); pl_[nf][1] = pk2(l2, l3);
        }

        // ---- O += P.V : 3 phases (Ph*Vh, Pl*Vh, Ph*Vl) ----
#pragma unroll
        for (int pv = 0; pv < 3; pv++) {
            uint32_t vbase = (pv == 2) ? vl_base : vh_base;
#pragma unroll
            for (int t = 0; t < 4; t++) {
                uint32_t a[4];
                if (pv == 1) {
                    a[0] = pl_[2 * t][0]; a[1] = pl_[2 * t][1];
                    a[2] = pl_[2 * t + 1][0]; a[3] = pl_[2 * t + 1][1];
                } else {
                    a[0] = ph_[2 * t][0]; a[1] = ph_[2 * t][1];
                    a[2] = ph_[2 * t + 1][0]; a[3] = ph_[2 * t + 1][1];
                }
#pragma unroll
                for (int nfvp = 0; nfvp < 4; nfvp++) {
                    uint32_t b0, b1, b2, b3;
                    LDMX4(b0, b1, b2, b3, vbase + nfvp * 2304 + t * 32);
                    uint32_t be[2] = { b0, b2 };
                    uint32_t bo[2] = { b1, b3 };
                    mma16816(oc[2 * nfvp],     a, be);
                    mma16816(oc[2 * nfvp + 1], a, bo);
                }
            }
        }
    }

    l_i[0] += __shfl_xor_sync(0xffffffffu, l_i[0], 1);
    l_i[0] += __shfl_xor_sync(0xffffffffu, l_i[0], 2);
    l_i[1] += __shfl_xor_sync(0xffffffffu, l_i[1], 1);
    l_i[1] += __shfl_xor_sync(0xffffffffu, l_i[1], 2);
    float inv0 = 1.0f / l_i[0], inv1 = 1.0f / l_i[1];

    int b = bh >> 3, h = bh & 7;
    int l0r = i0 + wid * 16 + qr;
    size_t base0 = (size_t)(b * NL + l0r) * GK;
    size_t base1 = (size_t)(b * NL + l0r + 8) * GK;
#pragma unroll
    for (int nfv = 0; nfv < 8; nfv++) {
        int col = h * 64 + nfv * 8 + 2 * lm4;
        float v0 = oc[nfv][0] * inv0, v1 = oc[nfv][1] * inv0;
        float w0 = oc[nfv][2] * inv1, w1 = oc[nfv][3] * inv1;
        __nv_bfloat16 vh0, vlo0, vh1, vlo1, wh0, wlo0, wh1, wlo1;
        bf16split(v0, vh0, vlo0); bf16split(v1, vh1, vlo1);
        bf16split(w0, wh0, wlo0); bf16split(w1, wh1, wlo1);
        *(uint32_t*)&g_Oc[base0 + col]        = pk2(vh0, vh1);
        *(uint32_t*)&g_Oc[base0 + 512 + col]  = pk2(vlo0, vlo1);
        *(uint32_t*)&g_Oc[base0 + 1024 + col] = pk2(vh0, vh1);
        *(uint32_t*)&g_Oc[base1 + col]        = pk2(wh0, wh1);
        *(uint32_t*)&g_Oc[base1 + 512 + col]  = pk2(wlo0, wlo1);
        *(uint32_t*)&g_Oc[base1 + 1024 + col] = pk2(wh0, wh1);
    }
}

// ---------------- launch -----------------------------------------------------
extern "C" void kernel_launch(void* const* d_in, const int* in_sizes, int n_in,
                              void* d_out, int out_size) {
    const float* features = (const float*)d_in[0];
    const float* ln_g = (const float*)d_in[2];
    const float* ln_b = (const float*)d_in[3];
    const float* wq  = (const float*)d_in[4];  const float* bq  = (const float*)d_in[5];
    const float* wk  = (const float*)d_in[6];  const float* bk  = (const float*)d_in[7];
    const float* wv  = (const float*)d_in[8];  const float* bv  = (const float*)d_in[9];
    const float* wqp = (const float*)d_in[10]; const float* bqp = (const float*)d_in[11];
    const float* wkp = (const float*)d_in[12]; const float* bkp = (const float*)d_in[13];
    const float* wo  = (const float*)d_in[16]; const float* bo  = (const float*)d_in[17];
    const float* pscale = (const float*)d_in[18];
    float* out = (float*)d_out;

    cudaFuncSetAttribute(gemm_cp<0>, cudaFuncAttributeMaxDynamicSharedMemorySize, GEMM_SMEM);
    cudaFuncSetAttribute(gemm_cp<1>, cudaFuncAttributeMaxDynamicSharedMemorySize, GEMM_SMEM);
    cudaFuncSetAttribute(flash_tc, cudaFuncAttributeMaxDynamicSharedMemorySize, FLASH_SMEM);

    pack_w<<<dim3(16, 72), 256>>>(wq, wk, wv, wqp, wkp, wo, pscale);
    pack_bias<<<7, 256>>>(bq, bk, bv, bqp, bkp, pscale);
    ln_kernel<<<NM, 256>>>(features, ln_g, ln_b);
    gemm_cp<0><<<dim3(NCOLP / 128, NM / 128), 256, GEMM_SMEM>>>(nullptr, nullptr);
    kbias_kernel<<<(NBH * NL + 255) / 256, 256>>>(pscale);
    flash_tc<<<dim3(NL / 64, NBH), 128, FLASH_SMEM>>>();
    gemm_cp<1><<<dim3(NC / 128, NM / 128), 256, GEMM_SMEM>>>(bo, out);
}

// round 7
// speedup vs baseline: 2.1964x; 1.1354x over previous
#include <cuda_runtime.h>
#include <cuda_bf16.h>
#include <cstdint>
#include <stdint.h>

// ---------------- problem constants -----------------------------------------
#define NL   1024
#define NC   512
#define NCOL 1728
#define NCOLP 1792
#define NM   2048
#define NBH  16
#define GK   1536        // split-concat K' = 3*512

// ---------------- scratch ----------------------------------------------------
__device__ float g_Kp[NBH * NL * 12];
__device__ float g_kb[NBH * NL];
__device__ float g_bias[NCOL];
__device__ __nv_bfloat16 g_xc[NM * GK];          // LN(x) [hi,lo,hi]
__device__ __nv_bfloat16 g_Wc[NCOLP * GK];       // packed W^T [hi,hi,lo]
__device__ __nv_bfloat16 g_Oc[NM * GK];          // attn out [hi,lo,hi]
__device__ __nv_bfloat16 g_WoC[NC * GK];         // wo^T [hi,hi,lo]
__device__ __nv_bfloat16 g_Qc[NBH * NL * 160];   // q_ext bf16 [hi|lo]; pads stay 0
__device__ __nv_bfloat16 g_Kc[NBH * NL * 160];
__device__ __nv_bfloat16 g_VhT[NBH * 64 * NL];   // V hi, transposed [bh*64+d][l]
__device__ __nv_bfloat16 g_VlT[NBH * 64 * NL];   // V lo, transposed

__device__ __forceinline__ void bf16split(float v, __nv_bfloat16& hi, __nv_bfloat16& lo) {
    hi = __float2bfloat16(v);
    lo = __float2bfloat16(v - __bfloat162float(hi));
}
__device__ __forceinline__ uint32_t pk2(__nv_bfloat16 a, __nv_bfloat16 b) {
    return (uint32_t)__bfloat16_as_ushort(a) | ((uint32_t)__bfloat16_as_ushort(b) << 16);
}
__device__ __forceinline__ uint32_t smem_u32(const void* p) {
    uint32_t a;
    asm("{ .reg .u64 t; cvta.to.shared.u64 t, %1; cvt.u32.u64 %0, t; }" : "=r"(a) : "l"(p));
    return a;
}
__device__ __forceinline__ void mma16816(float* c, const uint32_t* a, const uint32_t* b) {
    asm volatile("mma.sync.aligned.m16n8k16.row.col.f32.bf16.bf16.f32 "
                 "{%0,%1,%2,%3}, {%4,%5,%6,%7}, {%8,%9}, {%0,%1,%2,%3};"
                 : "+f"(c[0]), "+f"(c[1]), "+f"(c[2]), "+f"(c[3])
                 : "r"(a[0]), "r"(a[1]), "r"(a[2]), "r"(a[3]), "r"(b[0]), "r"(b[1]));
}
__device__ __forceinline__ void cpa16(uint32_t dst, const void* src) {
    asm volatile("cp.async.ca.shared.global [%0], [%1], 16;" :: "r"(dst), "l"(src));
}
#define CP_COMMIT() asm volatile("cp.async.commit_group;")
#define CP_WAIT1()  asm volatile("cp.async.wait_group 1;")
#define CP_WAIT0()  asm volatile("cp.async.wait_group 0;")
#define LDMX4(r0, r1, r2, r3, addr)                                                   \
    asm volatile("ldmatrix.sync.aligned.m8n8.x4.shared.b16 {%0,%1,%2,%3}, [%4];"      \
                 : "=r"(r0), "=r"(r1), "=r"(r2), "=r"(r3) : "r"(addr))

// ---------------- 1) pack weights via 32x32 smem transpose -------------------
__global__ void __launch_bounds__(256) pack_w(const float* __restrict__ wq,
                                              const float* __restrict__ wk,
                                              const float* __restrict__ wv,
                                              const float* __restrict__ wqp,
                                              const float* __restrict__ wkp,
                                              const float* __restrict__ wo,
                                              const float* __restrict__ pscale) {
    __shared__ float smt[32][33];
    int tx = threadIdx.x & 31, ty = threadIdx.x >> 5;
    int k0 = blockIdx.x * 32;
    int nt = blockIdx.y;
    if (nt < 56) {
        int n0 = nt * 32;
        const float* src; int ld, col;
        if (n0 < 512)       { src = wq;  ld = 512; col = n0; }
        else if (n0 < 1024) { src = wk;  ld = 512; col = n0 - 512; }
        else if (n0 < 1536) { src = wv;  ld = 512; col = n0 - 1024; }
        else if (n0 < 1632) { src = wqp; ld = 96;  col = n0 - 1536; }
        else if (n0 < 1728) { src = wkp; ld = 96;  col = n0 - 1632; }
        else                { src = nullptr; ld = 0; col = 0; }
#pragma unroll
        for (int i = 0; i < 4; i++) {
            int kr = ty + i * 8;
            smt[kr][tx] = src ? src[(size_t)(k0 + kr) * ld + col + tx] : 0.f;
        }
        __syncthreads();
#pragma unroll
        for (int i = 0; i < 4; i++) {
            int n = n0 + ty + i * 8, k = k0 + tx;
            float v = smt[tx][ty + i * 8];
            if (n < 512) v *= 0.125f;
            else if (n >= 1536 && n < 1632) v *= 2.0f * pscale[(n - 1536) / 12];
            __nv_bfloat16 hi, lo; bf16split(v, hi, lo);
            g_Wc[(size_t)n * GK + k]        = hi;
            g_Wc[(size_t)n * GK + 512 + k]  = hi;
            g_Wc[(size_t)n * GK + 1024 + k] = lo;
        }
    } else {
        int n0 = (nt - 56) * 32;
#pragma unroll
        for (int i = 0; i < 4; i++) {
            int kr = ty + i * 8;
            smt[kr][tx] = wo[(size_t)(k0 + kr) * 512 + n0 + tx];
        }
        __syncthreads();
#pragma unroll
        for (int i = 0; i < 4; i++) {
            int n = n0 + ty + i * 8, k = k0 + tx;
            __nv_bfloat16 hi, lo; bf16split(smt[tx][ty + i * 8], hi, lo);
            g_WoC[(size_t)n * GK + k]        = hi;
            g_WoC[(size_t)n * GK + 512 + k]  = hi;
            g_WoC[(size_t)n * GK + 1024 + k] = lo;
        }
    }
}

__global__ void pack_bias(const float* __restrict__ bq, const float* __restrict__ bk,
                          const float* __restrict__ bv, const float* __restrict__ bqp,
                          const float* __restrict__ bkp, const float* __restrict__ pscale) {
    int n = blockIdx.x * 256 + threadIdx.x;
    if (n >= NCOL) return;
    float bb;
    if (n < 512)        bb = bq[n] * 0.125f;
    else if (n < 1024)  bb = bk[n - 512];
    else if (n < 1536)  bb = bv[n - 1024];
    else if (n < 1632) { int c = n - 1536; bb = bqp[c] * 2.0f * pscale[c / 12]; }
    else               { int c = n - 1632; bb = bkp[c]; }
    g_bias[n] = bb;
}

// ---------------- 2) LayerNorm -> split-concat bf16 -------------------------
__global__ void ln_kernel(const float* __restrict__ f, const float* __restrict__ g,
                          const float* __restrict__ bb) {
    int row = blockIdx.x, t = threadIdx.x;
    const float* xr = f + (size_t)row * NC;
    float v0 = xr[t], v1 = xr[t + 256];
    float s = v0 + v1, s2 = v0 * v0 + v1 * v1;
#pragma unroll
    for (int o = 16; o > 0; o >>= 1) {
        s  += __shfl_xor_sync(0xffffffffu, s, o);
        s2 += __shfl_xor_sync(0xffffffffu, s2, o);
    }
    __shared__ float sh[16];
    if ((t & 31) == 0) { sh[t >> 5] = s; sh[8 + (t >> 5)] = s2; }
    __syncthreads();
    float ts = 0.f, ts2 = 0.f;
#pragma unroll
    for (int i = 0; i < 8; i++) { ts += sh[i]; ts2 += sh[8 + i]; }
    float mu   = ts * (1.0f / NC);
    float var  = ts2 * (1.0f / NC) - mu * mu;
    float rstd = rsqrtf(var + 1e-5f);
    float x0 = (v0 - mu) * rstd * g[t] + bb[t];
    float x1 = (v1 - mu) * rstd * g[t + 256] + bb[t + 256];
    size_t base = (size_t)row * GK;
    __nv_bfloat16 h0, l0, h1, l1;
    bf16split(x0, h0, l0); bf16split(x1, h1, l1);
    g_xc[base + t]        = h0;  g_xc[base + t + 256]        = h1;
    g_xc[base + 512 + t]  = l0;  g_xc[base + 512 + t + 256]  = l1;
    g_xc[base + 1024 + t] = h0;  g_xc[base + 1024 + t + 256] = h1;
}

// ---------------- 3) GEMM: ldmatrix + BK=64, 3-stage cp.async ----------------
// MT x 128 tile, 256 thr = 8 warps (2m x 4n).
template <int MODE, int MT>
__global__ void __launch_bounds__(256) gemm_cp(const float* __restrict__ bias2,
                                               float* __restrict__ outp) {
    constexpr int STAGE = (MT + 128) * 144;
    constexpr int MFRAG = MT / 32;
    constexpr int ITERS = (MT + 128) * 8 / 256;
    extern __shared__ char gsm[];
    uint32_t smBase = smem_u32(gsm);
    int tid = threadIdx.x, lane = tid & 31, wid = tid >> 5;
    int wm = wid & 1, wn = wid >> 1;
    int l16 = lane & 15, lh = lane >> 4;
    int m0 = blockIdx.y * MT, n0 = blockIdx.x * 128;
    const __nv_bfloat16* Ap = (MODE == 0 ? g_xc : g_Oc) + (size_t)m0 * GK;
    const __nv_bfloat16* Bp = (MODE == 0 ? g_Wc : g_WoC) + (size_t)n0 * GK;

#define GEMM_ISSUE(S) do {                                                         \
    int st_ = (S) % 3; int k0_ = (S) * 64;                                         \
    uint32_t base_ = smBase + st_ * STAGE;                                         \
    _Pragma("unroll")                                                              \
    for (int i_ = 0; i_ < ITERS; i_++) {                                           \
        int idx_ = tid + i_ * 256;                                                 \
        int row_ = idx_ >> 3, ch_ = idx_ & 7;                                      \
        const __nv_bfloat16* src_ = (row_ < MT)                                    \
            ? Ap + (size_t)row_ * GK + k0_ + ch_ * 8                               \
            : Bp + (size_t)(row_ - MT) * GK + k0_ + ch_ * 8;                       \
        cpa16(base_ + row_ * 144 + ch_ * 16, src_);                                \
    }                                                                              \
    CP_COMMIT();                                                                   \
} while (0)

    GEMM_ISSUE(0); GEMM_ISSUE(1);

    float c[MFRAG][4][4];
#pragma unroll
    for (int i = 0; i < MFRAG; i++)
#pragma unroll
        for (int j = 0; j < 4; j++)
#pragma unroll
            for (int e = 0; e < 4; e++) c[i][j][e] = 0.f;

    const int NS = GK / 64;   // 24
    for (int s = 0; s < NS; s++) {
        if (s + 2 < NS) CP_WAIT1(); else CP_WAIT0();
        __syncthreads();
        if (s + 2 < NS) GEMM_ISSUE(s + 2);
        uint32_t aB = smBase + (s % 3) * STAGE;
        uint32_t a_ad = aB + (wm * (MT / 2) + l16) * 144 + lh * 16;
        uint32_t b_ad = aB + MT * 144 + (wn * 32 + l16) * 144 + lh * 16;
#pragma unroll
        for (int ks = 0; ks < 4; ks++) {
            uint32_t a[MFRAG][4], bb[2][4];
#pragma unroll
            for (int mf = 0; mf < MFRAG; mf++)
                LDMX4(a[mf][0], a[mf][1], a[mf][2], a[mf][3], a_ad + mf * 2304 + ks * 32);
#pragma unroll
            for (int nfp = 0; nfp < 2; nfp++)
                LDMX4(bb[nfp][0], bb[nfp][1], bb[nfp][2], bb[nfp][3], b_ad + nfp * 2304 + ks * 32);
#pragma unroll
            for (int mf = 0; mf < MFRAG; mf++)
#pragma unroll
                for (int nfp = 0; nfp < 2; nfp++) {
                    uint32_t be[2] = { bb[nfp][0], bb[nfp][2] };
                    uint32_t bo[2] = { bb[nfp][1], bb[nfp][3] };
                    mma16816(c[mf][2 * nfp],     a[mf], be);
                    mma16816(c[mf][2 * nfp + 1], a[mf], bo);
                }
        }
    }
#undef GEMM_ISSUE

    // epilogue
#pragma unroll
    for (int mf = 0; mf < MFRAG; mf++) {
#pragma unroll
        for (int nf = 0; nf < 4; nf++) {
#pragma unroll
            for (int ep = 0; ep < 2; ep++) {
                int m = m0 + wm * (MT / 2) + mf * 16 + (lane >> 2) + ep * 8;
                int n = n0 + wn * 32 + nf * 8 + (lane & 3) * 2;
                float v0 = c[mf][nf][ep * 2 + 0];
                float v1 = c[mf][nf][ep * 2 + 1];
                if (MODE == 0) {
                    if (n < NCOL) {
                        v0 += g_bias[n]; v1 += g_bias[n + 1];
                        int b = m >> 10, l = m & 1023;
                        __nv_bfloat16 h0, lo0, h1, lo1;
                        bf16split(v0, h0, lo0); bf16split(v1, h1, lo1);
                        if (n < 512) {
                            int h = n >> 6, d = n & 63;
                            size_t row = (size_t)((b * 8 + h) * NL + l) * 160;
                            *(uint32_t*)&g_Qc[row + d]      = pk2(h0, h1);
                            *(uint32_t*)&g_Qc[row + 80 + d] = pk2(lo0, lo1);
                        } else if (n < 1024) {
                            int n2 = n - 512; int h = n2 >> 6, d = n2 & 63;
                            size_t row = (size_t)((b * 8 + h) * NL + l) * 160;
                            *(uint32_t*)&g_Kc[row + d]      = pk2(h0, h1);
                            *(uint32_t*)&g_Kc[row + 80 + d] = pk2(lo0, lo1);
                        } else if (n < 1536) {
                            int n2 = n - 1024; int h = n2 >> 6, d = n2 & 63;
                            size_t vb = (size_t)((b * 8 + h) * 64 + d) * NL + l;
                            g_VhT[vb]      = h0;
                            g_VhT[vb + NL] = h1;
                            g_VlT[vb]      = lo0;
                            g_VlT[vb + NL] = lo1;
                        } else if (n < 1632) {
                            int cc = n - 1536; int h = cc / 12, r = cc - h * 12;
                            size_t row = (size_t)((b * 8 + h) * NL + l) * 160;
                            *(uint32_t*)&g_Qc[row + 64 + r]  = pk2(h0, h1);
                            *(uint32_t*)&g_Qc[row + 144 + r] = pk2(lo0, lo1);
                        } else {
                            int cc = n - 1632; int h = cc / 12, r = cc - h * 12;
                            size_t row = (size_t)((b * 8 + h) * NL + l);
                            *(uint32_t*)&g_Kc[row * 160 + 64 + r]  = pk2(h0, h1);
                            *(uint32_t*)&g_Kc[row * 160 + 144 + r] = pk2(lo0, lo1);
                            *(float2*)&g_Kp[row * 12 + r] = make_float2(v0, v1);
                        }
                    }
                } else {
                    *(float2*)&outp[(size_t)m * NC + n] =
                        make_float2(v0 + bias2[n], v1 + bias2[n + 1]);
                }
            }
        }
    }
}

// ---------------- 4) key bias -----------------------------------------------
__global__ void kbias_kernel(const float* __restrict__ pscale) {
    int row = blockIdx.x * blockDim.x + threadIdx.x;
    if (row >= NBH * NL) return;
    int h = (row >> 10) & 7;
    float s = 0.f;
#pragma unroll
    for (int r = 0; r < 12; r++) { float v = g_Kp[row * 12 + r]; s += v * v; }
    g_kb[row] = -pscale[h] * s;
}

// ---------------- 5) flash attention: cp.async double-buffered ---------------
// smem: Qs 21504 | buf{0,1}: Ks 21504, Vh 9216, Vl 9216, kbs 256 (=40192 each)
#define FBUF0 21504
#define FBUFSZ 40192
#define FV_OFF 21504
#define FVL_OFF 30720
#define FKB_OFF 39936
#define FLASH_SMEM (21504 + 2 * FBUFSZ)

__global__ void __launch_bounds__(128) flash_tc() {
    extern __shared__ char fsm[];
    __nv_bfloat16* Qs = (__nv_bfloat16*)fsm;
    uint32_t sm = smem_u32(fsm);

    int tid = threadIdx.x, lane = tid & 31, wid = tid >> 5;
    int l16 = lane & 15, lh = lane >> 4;
    int bh = blockIdx.y, i0 = blockIdx.x << 6;

    const __nv_bfloat16* Qg = g_Qc + (size_t)(bh * NL + i0) * 160;
    const __nv_bfloat16* Kg0 = g_Kc + (size_t)(bh * NL) * 160;
    const __nv_bfloat16* VhG = g_VhT + (size_t)(bh * 64) * NL;
    const __nv_bfloat16* VlG = g_VlT + (size_t)(bh * 64) * NL;
    const float* kbG = g_kb + bh * NL;

#define FISSUE(KT) do {                                                              \
    int j0_ = (KT) << 6;                                                             \
    uint32_t bufb_ = sm + FBUF0 + ((KT) & 1) * FBUFSZ;                               \
    const __nv_bfloat16* Kg_ = Kg0 + (size_t)j0_ * 160;                              \
    _Pragma("unroll")                                                                \
    for (int i_ = 0; i_ < 10; i_++) {                                                \
        int idx_ = tid + i_ * 128;                                                   \
        int row_ = idx_ / 20, ch_ = idx_ % 20;                                       \
        cpa16(bufb_ + row_ * 336 + ch_ * 16, Kg_ + row_ * 160 + ch_ * 8);            \
    }                                                                                \
    _Pragma("unroll")                                                                \
    for (int i_ = 0; i_ < 4; i_++) {                                                 \
        int idx_ = tid + i_ * 128;                                                   \
        int d_ = idx_ >> 3, ch_ = idx_ & 7;                                          \
        cpa16(bufb_ + FV_OFF + d_ * 144 + ch_ * 16, VhG + (size_t)d_ * NL + j0_ + ch_ * 8); \
        cpa16(bufb_ + FVL_OFF + d_ * 144 + ch_ * 16, VlG + (size_t)d_ * NL + j0_ + ch_ * 8); \
    }                                                                                \
    if (tid < 16) cpa16(bufb_ + FKB_OFF + tid * 16, kbG + j0_ + tid * 4);            \
    CP_COMMIT();                                                                     \
} while (0)

    FISSUE(0);

    for (int idx = tid; idx < 64 * 20; idx += 128) {
        int row = idx / 20, ch = idx % 20;
        *(uint4*)&Qs[row * 168 + ch * 8] = *(const uint4*)(Qg + row * 160 + ch * 8);
    }
    uint32_t qa_base = sm + (wid * 16 + l16) * 336 + lh * 16;

    float oc[8][4];
#pragma unroll
    for (int i = 0; i < 8; i++)
#pragma unroll
        for (int e = 0; e < 4; e++) oc[i][e] = 0.f;
    float l_i[2] = {0.f, 0.f};
    int qr = lane >> 2, lm4 = lane & 3;

    for (int kt = 0; kt < 16; kt++) {
        CP_WAIT0();
        __syncthreads();
        if (kt + 1 < 16) FISSUE(kt + 1);

        uint32_t bufb = sm + FBUF0 + (kt & 1) * FBUFSZ;
        uint32_t kb_base = bufb + l16 * 336 + lh * 16;
        uint32_t vh_base = bufb + FV_OFF + l16 * 144 + lh * 16;
        uint32_t vl_base = bufb + FVL_OFF + l16 * 144 + lh * 16;
        const float* kbs = (const float*)(fsm + (FBUF0 - 0) + (kt & 1) * FBUFSZ + FKB_OFF);

        // ---- S = Q_ext . K_ext^T : 3 phases (hh, lh, hl) ----
        float sc[8][4];
#pragma unroll
        for (int i = 0; i < 8; i++)
#pragma unroll
            for (int e = 0; e < 4; e++) sc[i][e] = 0.f;

#pragma unroll
        for (int ph = 0; ph < 3; ph++) {
            uint32_t qoff = (ph == 1) ? 160u : 0u;
            uint32_t koff = (ph == 2) ? 160u : 0u;
#pragma unroll
            for (int ks = 0; ks < 5; ks++) {
                uint32_t a[4];
                LDMX4(a[0], a[1], a[2], a[3], qa_base + qoff + ks * 32);
#pragma unroll
                for (int nfp = 0; nfp < 4; nfp++) {
                    uint32_t b0, b1, b2, b3;
                    LDMX4(b0, b1, b2, b3, kb_base + nfp * 5376 + koff + ks * 32);
                    uint32_t be[2] = { b0, b2 };
                    uint32_t bo[2] = { b1, b3 };
                    mma16816(sc[2 * nfp],     a, be);
                    mma16816(sc[2 * nfp + 1], a, bo);
                }
            }
        }

        // ---- bias + exp + pack P in-register ----
        uint32_t ph_[8][2], pl_[8][2];
#pragma unroll
        for (int nf = 0; nf < 8; nf++) {
            int k0 = nf * 8 + 2 * lm4;
            float kb0 = kbs[k0], kb1 = kbs[k0 + 1];
            float e0 = __expf(sc[nf][0] + kb0);
            float e1 = __expf(sc[nf][1] + kb1);
            float e2 = __expf(sc[nf][2] + kb0);
            float e3 = __expf(sc[nf][3] + kb1);
            l_i[0] += e0 + e1;
            l_i[1] += e2 + e3;
            __nv_bfloat16 h0, l0, h1, l1, h2, l2, h3, l3;
            bf16split(e0, h0, l0); bf16split(e1, h1, l1);
            bf16split(e2, h2, l2); bf16split(e3, h3, l3);
            ph_[nf][0] = pk2(h0, h1); ph_[nf][1] = pk2(h2, h3);
            pl_[nf][0] = pk2(l0, l1); pl_[nf][1] = pk2(l2, l3);
        }

        // ---- O += P.V : 3 phases (Ph*Vh, Pl*Vh, Ph*Vl) ----
#pragma unroll
        for (int pv = 0; pv < 3; pv++) {
            uint32_t vbase = (pv == 2) ? vl_base : vh_base;
#pragma unroll
            for (int t = 0; t < 4; t++) {
                uint32_t a[4];
                if (pv == 1) {
                    a[0] = pl_[2 * t][0]; a[1] = pl_[2 * t][1];
                    a[2] = pl_[2 * t + 1][0]; a[3] = pl_[2 * t + 1][1];
                } else {
                    a[0] = ph_[2 * t][0]; a[1] = ph_[2 * t][1];
                    a[2] = ph_[2 * t + 1][0]; a[3] = ph_[2 * t + 1][1];
                }
#pragma unroll
                for (int nfvp = 0; nfvp < 4; nfvp++) {
                    uint32_t b0, b1, b2, b3;
                    LDMX4(b0, b1, b2, b3, vbase + nfvp * 2304 + t * 32);
                    uint32_t be[2] = { b0, b2 };
                    uint32_t bo[2] = { b1, b3 };
                    mma16816(oc[2 * nfvp],     a, be);
                    mma16816(oc[2 * nfvp + 1], a, bo);
                }
            }
        }
    }
#undef FISSUE

    l_i[0] += __shfl_xor_sync(0xffffffffu, l_i[0], 1);
    l_i[0] += __shfl_xor_sync(0xffffffffu, l_i[0], 2);
    l_i[1] += __shfl_xor_sync(0xffffffffu, l_i[1], 1);
    l_i[1] += __shfl_xor_sync(0xffffffffu, l_i[1], 2);
    float inv0 = 1.0f / l_i[0], inv1 = 1.0f / l_i[1];

    int b = bh >> 3, h = bh & 7;
    int l0r = i0 + wid * 16 + qr;
    size_t base0 = (size_t)(b * NL + l0r) * GK;
    size_t base1 = (size_t)(b * NL + l0r + 8) * GK;
#pragma unroll
    for (int nfv = 0; nfv < 8; nfv++) {
        int col = h * 64 + nfv * 8 + 2 * lm4;
        float v0 = oc[nfv][0] * inv0, v1 = oc[nfv][1] * inv0;
        float w0 = oc[nfv][2] * inv1, w1 = oc[nfv][3] * inv1;
        __nv_bfloat16 vh0, vlo0, vh1, vlo1, wh0, wlo0, wh1, wlo1;
        bf16split(v0, vh0, vlo0); bf16split(v1, vh1, vlo1);
        bf16split(w0, wh0, wlo0); bf16split(w1, wh1, wlo1);
        *(uint32_t*)&g_Oc[base0 + col]        = pk2(vh0, vh1);
        *(uint32_t*)&g_Oc[base0 + 512 + col]  = pk2(vlo0, vlo1);
        *(uint32_t*)&g_Oc[base0 + 1024 + col] = pk2(vh0, vh1);
        *(uint32_t*)&g_Oc[base1 + col]        = pk2(wh0, wh1);
        *(uint32_t*)&g_Oc[base1 + 512 + col]  = pk2(wlo0, wlo1);
        *(uint32_t*)&g_Oc[base1 + 1024 + col] = pk2(wh0, wh1);
    }
}

// ---------------- launch -----------------------------------------------------
extern "C" void kernel_launch(void* const* d_in, const int* in_sizes, int n_in,
                              void* d_out, int out_size) {
    const float* features = (const float*)d_in[0];
    const float* ln_g = (const float*)d_in[2];
    const float* ln_b = (const float*)d_in[3];
    const float* wq  = (const float*)d_in[4];  const float* bq  = (const float*)d_in[5];
    const float* wk  = (const float*)d_in[6];  const float* bk  = (const float*)d_in[7];
    const float* wv  = (const float*)d_in[8];  const float* bv  = (const float*)d_in[9];
    const float* wqp = (const float*)d_in[10]; const float* bqp = (const float*)d_in[11];
    const float* wkp = (const float*)d_in[12]; const float* bkp = (const float*)d_in[13];
    const float* wo  = (const float*)d_in[16]; const float* bo  = (const float*)d_in[17];
    const float* pscale = (const float*)d_in[18];
    float* out = (float*)d_out;

    const int SMEM0 = (128 + 128) * 144 * 3;   // 110592
    const int SMEM1 = (64 + 128) * 144 * 3;    // 82944
    cudaFuncSetAttribute(gemm_cp<0, 128>, cudaFuncAttributeMaxDynamicSharedMemorySize, SMEM0);
    cudaFuncSetAttribute(gemm_cp<1, 64>,  cudaFuncAttributeMaxDynamicSharedMemorySize, SMEM1);
    cudaFuncSetAttribute(flash_tc, cudaFuncAttributeMaxDynamicSharedMemorySize, FLASH_SMEM);

    pack_w<<<dim3(16, 72), 256>>>(wq, wk, wv, wqp, wkp, wo, pscale);
    pack_bias<<<7, 256>>>(bq, bk, bv, bqp, bkp, pscale);
    ln_kernel<<<NM, 256>>>(features, ln_g, ln_b);
    gemm_cp<0, 128><<<dim3(NCOLP / 128, NM / 128), 256, SMEM0>>>(nullptr, nullptr);
    kbias_kernel<<<(NBH * NL + 255) / 256, 256>>>(pscale);
    flash_tc<<<dim3(NL / 64, NBH), 128, FLASH_SMEM>>>();
    gemm_cp<1, 64><<<dim3(NC / 128, NM / 64), 256, SMEM1>>>(bo, out);
}